// round 2
// baseline (speedup 1.0000x reference)
#include <cuda_runtime.h>
#include <math.h>

#define NNODE 50000
#define DIM   128
#define NEDGE 400000
#define NHEAD 8

// ------------------------- device scratch (no allocs allowed) -------------------------
__device__ float g_Ku[NNODE*DIM];
__device__ float g_Ki[NNODE*DIM];
__device__ float g_Qu[NNODE*DIM];
__device__ float g_Qi[NNODE*DIM];
__device__ float g_Vru[NNODE*DIM];
__device__ float g_Vri[NNODE*DIM];
__device__ float g_Vtu[NNODE*DIM];
__device__ float g_Vti[NNODE*DIM];
__device__ float g_ltu[NNODE*DIM];
__device__ float g_htu[NNODE*DIM];
__device__ float g_lti[NNODE*DIM];
__device__ float g_hti[NNODE*DIM];
__device__ float g_HZ0[NNODE*DIM];
__device__ float g_HZ1[NNODE*DIM];
__device__ float g_XP[NNODE*DIM];
__device__ float g_T[NNODE*DIM];
__device__ float g_raw[(size_t)NEDGE*NHEAD];
__device__ int   g_counts[NNODE];
__device__ int   g_cursor[NNODE];
__device__ int   g_offsets[NNODE+1];
__device__ int   g_elist[NEDGE];
__device__ float g_fWku[DIM*DIM];
__device__ float g_fbku[DIM];
__device__ float g_fWki[DIM*DIM];
__device__ float g_fbki[DIM];

// ------------------------- f32x2 packed-FMA helpers -------------------------
__device__ __forceinline__ unsigned long long pk2(float lo, float hi) {
    unsigned long long r;
    asm("mov.b64 %0, {%1, %2};" : "=l"(r) : "f"(lo), "f"(hi));
    return r;
}
__device__ __forceinline__ void upk2(unsigned long long v, float &lo, float &hi) {
    asm("mov.b64 {%0, %1}, %2;" : "=f"(lo), "=f"(hi) : "l"(v));
}
__device__ __forceinline__ void ffma2(unsigned long long &d, unsigned long long a, unsigned long long b) {
    asm("fma.rn.f32x2 %0, %1, %2, %0;" : "+l"(d) : "l"(a), "l"(b));
}

// ------------------------- zero an int buffer (graph-capture-safe) -------------------------
__global__ void zero_ints(int* __restrict__ p, int n) {
    int i = blockIdx.x * blockDim.x + threadIdx.x;
    if (i < n) p[i] = 0;
}

// ------------------------- fused K-weight build: Wk' = Wk @ blockdiag(rel_att) -------------------------
__global__ void fuse_k(const float* __restrict__ Wk, const float* __restrict__ bk,
                       const float* __restrict__ ra, float* __restrict__ fW, float* __restrict__ fb) {
    int idx = blockIdx.x * blockDim.x + threadIdx.x;
    if (idx < DIM * DIM) {
        int j = idx >> 7, c = idx & 127;
        int h = c >> 4, k = c & 15;
        float s = 0.f;
#pragma unroll
        for (int d = 0; d < 16; d++)
            s += Wk[(j << 7) + (h << 4) + d] * ra[(h * 16 + d) * 16 + k];
        fW[idx] = s;
    } else if (idx < DIM * DIM + DIM) {
        int c = idx - DIM * DIM;
        int h = c >> 4, k = c & 15;
        float s = 0.f;
#pragma unroll
        for (int d = 0; d < 16; d++)
            s += bk[(h << 4) + d] * ra[(h * 16 + d) * 16 + k];
        fb[c] = s;
    }
}

// ------------------------- Y = X @ blockdiag(rel_msg) (per-head 16x16) -------------------------
__global__ void blockdiag(const float* __restrict__ X, const float* __restrict__ RM,
                          float* __restrict__ Y, int N) {
    __shared__ float sm[NHEAD * 16 * 16];
    for (int i = threadIdx.x; i < NHEAD * 256; i += blockDim.x) sm[i] = RM[i];
    __syncthreads();
    int idx = blockIdx.x * blockDim.x + threadIdx.x;
    if (idx >= N * DIM) return;
    int c = idx & 127;
    int h = c >> 4, kk = c & 15;
    const float* xr = X + (idx & ~127) + (h << 4);
    const float* m = sm + h * 256 + kk;
    float s = 0.f;
#pragma unroll
    for (int d = 0; d < 16; d++) s += xr[d] * m[d * 16];
    Y[idx] = s;
}

// ------------------------- tiled fp32 GEMM: C[N,128] = op(A,A2) @ W + bias -------------------------
// MIN_: 0 -> A ; 1 -> A+A2 ; 2 -> A-A2.   ACT_: 0 none, 1 tanh.
// MOUT_: 0 plain ; 1 -> C = (..)*sigmoid(*skipp) + Dres*(1-sigmoid(*skipp))
template<int MIN_, int ACT_, int MOUT_>
__global__ __launch_bounds__(256) void gemm128(
    const float* __restrict__ A, const float* __restrict__ A2,
    const float* __restrict__ W, const float* __restrict__ bias,
    const float* __restrict__ Dres, const float* __restrict__ skipp,
    float* __restrict__ C, int N)
{
    __shared__ __align__(16) float As[32][64];   // transposed: As[k][m]
    __shared__ __align__(16) float Ws[32][128];
    const int tid = threadIdx.x;
    const int tx = tid & 31, ty = tid >> 5;
    const int rowBase = blockIdx.x * 64;

    unsigned long long acc[8][2];
#pragma unroll
    for (int r = 0; r < 8; r++) { acc[r][0] = 0ull; acc[r][1] = 0ull; }

    for (int k0 = 0; k0 < DIM; k0 += 32) {
#pragma unroll
        for (int i = 0; i < 2; i++) {
            int row = (tid >> 3) + i * 32;
            int c4 = (tid & 7) * 4;
            int grow = rowBase + row;
            float4 v = make_float4(0.f, 0.f, 0.f, 0.f);
            if (grow < N) {
                v = *(const float4*)(A + (size_t)grow * DIM + k0 + c4);
                if (MIN_ == 1) {
                    float4 b = *(const float4*)(A2 + (size_t)grow * DIM + k0 + c4);
                    v.x += b.x; v.y += b.y; v.z += b.z; v.w += b.w;
                } else if (MIN_ == 2) {
                    float4 b = *(const float4*)(A2 + (size_t)grow * DIM + k0 + c4);
                    v.x -= b.x; v.y -= b.y; v.z -= b.z; v.w -= b.w;
                }
            }
            As[c4 + 0][row] = v.x; As[c4 + 1][row] = v.y;
            As[c4 + 2][row] = v.z; As[c4 + 3][row] = v.w;
        }
#pragma unroll
        for (int i = 0; i < 4; i++) {
            int kr = (tid >> 5) + i * 8;
            *(float4*)&Ws[kr][(tid & 31) * 4] =
                *(const float4*)(W + (size_t)(k0 + kr) * DIM + (tid & 31) * 4);
        }
        __syncthreads();
#pragma unroll
        for (int k = 0; k < 32; k++) {
            float4 a0 = *(float4*)&As[k][ty * 8];
            float4 a1 = *(float4*)&As[k][ty * 8 + 4];
            float4 w  = *(float4*)&Ws[k][tx * 4];
            unsigned long long wp0 = pk2(w.x, w.y);
            unsigned long long wp1 = pk2(w.z, w.w);
            float ar[8] = {a0.x, a0.y, a0.z, a0.w, a1.x, a1.y, a1.z, a1.w};
#pragma unroll
            for (int r = 0; r < 8; r++) {
                unsigned long long ap = pk2(ar[r], ar[r]);
                ffma2(acc[r][0], ap, wp0);
                ffma2(acc[r][1], ap, wp1);
            }
        }
        __syncthreads();
    }

    float alpha = 1.f, oneMinus = 0.f;
    if (MOUT_ == 1) {
        float s = *skipp;
        alpha = 1.f / (1.f + __expf(-s));
        oneMinus = 1.f - alpha;
    }
    const int col = tx * 4;
    float b0 = bias[col], b1 = bias[col + 1], b2 = bias[col + 2], b3 = bias[col + 3];
#pragma unroll
    for (int r = 0; r < 8; r++) {
        int grow = rowBase + ty * 8 + r;
        if (grow < N) {
            float o0, o1, o2, o3;
            upk2(acc[r][0], o0, o1); upk2(acc[r][1], o2, o3);
            o0 += b0; o1 += b1; o2 += b2; o3 += b3;
            if (ACT_ == 1) { o0 = tanhf(o0); o1 = tanhf(o1); o2 = tanhf(o2); o3 = tanhf(o3); }
            if (MOUT_ == 1) {
                const float* dr = Dres + (size_t)grow * DIM + col;
                o0 = o0 * alpha + dr[0] * oneMinus;
                o1 = o1 * alpha + dr[1] * oneMinus;
                o2 = o2 * alpha + dr[2] * oneMinus;
                o3 = o3 * alpha + dr[3] * oneMinus;
            }
            *(float4*)(C + (size_t)grow * DIM + col) = make_float4(o0, o1, o2, o3);
        }
    }
}

// ------------------------- CSR build -------------------------
__global__ void count_edges(const int* __restrict__ dst, int* __restrict__ counts) {
    int e = blockIdx.x * blockDim.x + threadIdx.x;
    if (e < NEDGE) atomicAdd(&counts[dst[e]], 1);
}

__global__ void scan_offsets(const int* __restrict__ counts, int* __restrict__ offsets, int n) {
    __shared__ int sh[1024];
    __shared__ int carry;
    int tid = threadIdx.x;
    if (tid == 0) { carry = 0; offsets[0] = 0; }
    __syncthreads();
    for (int base = 0; base < n; base += 1024) {
        int i = base + tid;
        int v = (i < n) ? counts[i] : 0;
        sh[tid] = v;
        __syncthreads();
        for (int off = 1; off < 1024; off <<= 1) {
            int t = (tid >= off) ? sh[tid - off] : 0;
            __syncthreads();
            sh[tid] += t;
            __syncthreads();
        }
        int incl = sh[tid] + carry;
        if (i < n) offsets[i + 1] = incl;
        __syncthreads();
        if (tid == 1023) carry = incl;
        __syncthreads();
    }
}

__global__ void scatter_edges(const int* __restrict__ src, const int* __restrict__ dst,
                              const int* __restrict__ offsets, int* __restrict__ cursor,
                              int* __restrict__ elist) {
    int e = blockIdx.x * blockDim.x + threadIdx.x;
    if (e < NEDGE) {
        int d = dst[e];
        int p = atomicAdd(&cursor[d], 1);
        elist[offsets[d] + p] = src[e];   // store SRC id; slot order within a segment is irrelevant
    }
}

// ------------------------- per-dst edge softmax (both branches) + aggregation -------------------------
// one warp per destination node; lane l owns features [4l,4l+4), head = l>>2
__global__ void attn_agg(const float* __restrict__ Q, const float* __restrict__ K,
                         const float* __restrict__ V,
                         const int* __restrict__ offsets, const int* __restrict__ elist,
                         const float* __restrict__ pri,
                         float* __restrict__ rawb,
                         float* __restrict__ lt_out, float* __restrict__ ht_out, int Ndst)
{
    int warp = (blockIdx.x * blockDim.x + threadIdx.x) >> 5;
    int lane = threadIdx.x & 31;
    if (warp >= Ndst) return;
    const int beg = offsets[warp], end = offsets[warp + 1];
    const int h = lane >> 2;
    const float scale = pri[h] * 0.25f;   // rel_pri[h] / sqrt(16)
    float4 q = *(const float4*)(Q + (size_t)warp * DIM + lane * 4);

    float m_lf = __int_as_float(0xff800000);
    float m_hf = m_lf;
    // pass 1: raw scores + exact per-head maxes of both branches
    for (int e = beg; e < end; e++) {
        int s = elist[e];
        float4 kv = *(const float4*)(K + (size_t)s * DIM + lane * 4);
        float p = q.x * kv.x + q.y * kv.y + q.z * kv.z + q.w * kv.w;
        p += __shfl_xor_sync(0xffffffffu, p, 1);
        p += __shfl_xor_sync(0xffffffffu, p, 2);
        float raw = p * scale;
        if ((lane & 3) == 0) rawb[(size_t)e * NHEAD + h] = raw;
        m_lf = fmaxf(m_lf, raw);
        m_hf = fmaxf(m_hf, 1.0f / (raw + 1e-6f));
    }
    // pass 2: unnormalized weighted sums + partition functions
    float z_lf = 0.f, z_hf = 0.f;
    float4 alt = make_float4(0.f, 0.f, 0.f, 0.f);
    float4 aht = make_float4(0.f, 0.f, 0.f, 0.f);
    for (int e = beg; e < end; e++) {
        int s = elist[e];
        float rl = 0.f;
        if ((lane & 3) == 0) rl = rawb[(size_t)e * NHEAD + h];
        float raw = __shfl_sync(0xffffffffu, rl, lane & ~3);
        float elf = __expf(raw - m_lf);
        float ehf = __expf(1.0f / (raw + 1e-6f) - m_hf);
        z_lf += elf; z_hf += ehf;
        float4 v = *(const float4*)(V + (size_t)s * DIM + lane * 4);
        alt.x += v.x * elf; alt.y += v.y * elf; alt.z += v.z * elf; alt.w += v.w * elf;
        aht.x += v.x * ehf; aht.y += v.y * ehf; aht.z += v.z * ehf; aht.w += v.w * ehf;
    }
    float izl = (end > beg) ? 1.0f / z_lf : 0.f;
    float izh = (end > beg) ? 1.0f / z_hf : 0.f;
    *(float4*)(lt_out + (size_t)warp * DIM + lane * 4) =
        make_float4(alt.x * izl, alt.y * izl, alt.z * izl, alt.w * izl);
    *(float4*)(ht_out + (size_t)warp * DIM + lane * 4) =
        make_float4(aht.x * izh, aht.y * izh, aht.z * izh, aht.w * izh);
}

// ------------------------- gate scores + blended T (warp per node) -------------------------
__global__ void compute_T(const float* __restrict__ Vr, const float* __restrict__ lta,
                          const float* __restrict__ hta, const float* __restrict__ HZ0,
                          const float* __restrict__ HZ1, const float* __restrict__ XP,
                          float* __restrict__ T, int N)
{
    int warp = (blockIdx.x * blockDim.x + threadIdx.x) >> 5;
    int lane = threadIdx.x & 31;
    if (warp >= N) return;
    size_t base = (size_t)warp * DIM + lane * 4;
    float4 hz0 = *(const float4*)(HZ0 + base);
    float4 hz1 = *(const float4*)(HZ1 + base);
    float4 xp  = *(const float4*)(XP + base);
    float s0 = hz0.x * xp.x + hz0.y * xp.y + hz0.z * xp.z + hz0.w * xp.w;
    float s1 = hz1.x * xp.x + hz1.y * xp.y + hz1.z * xp.z + hz1.w * xp.w;
#pragma unroll
    for (int o = 16; o > 0; o >>= 1) {
        s0 += __shfl_xor_sync(0xffffffffu, s0, o);
        s1 += __shfl_xor_sync(0xffffffffu, s1, o);
    }
    float m = fmaxf(s0, s1);
    float e0 = __expf(s0 - m), e1 = __expf(s1 - m);
    float inv = 1.0f / (e0 + e1);
    float sc0 = e0 * inv, sc1 = e1 * inv;
    float4 ori = *(const float4*)(Vr + base);
    float4 la  = *(const float4*)(lta + base);
    float4 ha  = *(const float4*)(hta + base);
    float4 t;
    t.x = (ori.x + la.x) * sc0 + (ori.x - ha.x) * sc1;
    t.y = (ori.y + la.y) * sc0 + (ori.y - ha.y) * sc1;
    t.z = (ori.z + la.z) * sc0 + (ori.z - ha.z) * sc1;
    t.w = (ori.w + la.w) * sc0 + (ori.w - ha.w) * sc1;
    *(float4*)(T + base) = t;
}

// ------------------------- launch -------------------------
extern "C" void kernel_launch(void* const* d_in, const int* in_sizes, int n_in,
                              void* d_out, int out_size) {
    const float* h_user = (const float*)d_in[0];
    const float* h_item = (const float*)d_in[1];
    const int* buys_src = (const int*)d_in[2];
    const int* buys_dst = (const int*)d_in[3];
    const int* rev_src  = (const int*)d_in[4];
    const int* rev_dst  = (const int*)d_in[5];
    const float* Wk_u = (const float*)d_in[6];  const float* bk_u = (const float*)d_in[7];
    const float* Wk_i = (const float*)d_in[8];  const float* bk_i = (const float*)d_in[9];
    const float* Wq_u = (const float*)d_in[10]; const float* bq_u = (const float*)d_in[11];
    const float* Wq_i = (const float*)d_in[12]; const float* bq_i = (const float*)d_in[13];
    const float* Wv_u = (const float*)d_in[14]; const float* bv_u = (const float*)d_in[15];
    const float* Wv_i = (const float*)d_in[16]; const float* bv_i = (const float*)d_in[17];
    const float* Wa_u = (const float*)d_in[18]; const float* ba_u = (const float*)d_in[19];
    const float* Wa_i = (const float*)d_in[20]; const float* ba_i = (const float*)d_in[21];
    const float* Wf = (const float*)d_in[22];   const float* bf = (const float*)d_in[23];
    const float* Wx = (const float*)d_in[24];   const float* bx = (const float*)d_in[25];
    const float* rel_pri = (const float*)d_in[26];
    const float* rel_att = (const float*)d_in[27];
    const float* rel_msg = (const float*)d_in[28];
    const float* skip = (const float*)d_in[29];
    float* out_u = (float*)d_out;
    float* out_i = (float*)d_out + (size_t)NNODE * DIM;

    float *Ku, *Ki, *Qu, *Qi, *Vru, *Vri, *Vtu, *Vti;
    float *ltu, *htu, *lti, *hti, *HZ0, *HZ1, *XP, *T, *rawb;
    float *fWku, *fbku, *fWki, *fbki;
    int *counts, *cursor, *offsets, *elist;
#define SYM(p, s) cudaGetSymbolAddress((void**)&p, s)
    SYM(Ku, g_Ku); SYM(Ki, g_Ki); SYM(Qu, g_Qu); SYM(Qi, g_Qi);
    SYM(Vru, g_Vru); SYM(Vri, g_Vri); SYM(Vtu, g_Vtu); SYM(Vti, g_Vti);
    SYM(ltu, g_ltu); SYM(htu, g_htu); SYM(lti, g_lti); SYM(hti, g_hti);
    SYM(HZ0, g_HZ0); SYM(HZ1, g_HZ1); SYM(XP, g_XP); SYM(T, g_T); SYM(rawb, g_raw);
    SYM(counts, g_counts); SYM(cursor, g_cursor); SYM(offsets, g_offsets); SYM(elist, g_elist);
    SYM(fWku, g_fWku); SYM(fbku, g_fbku); SYM(fWki, g_fWki); SYM(fbki, g_fbki);
#undef SYM

    const int gemmGrid = (NNODE + 63) / 64;
    const int fuseGrid = (DIM * DIM + DIM + 255) / 256;
    const int bdGrid = (NNODE * DIM + 255) / 256;
    const int edgeGrid = (NEDGE + 255) / 256;
    const int warpGrid = (NNODE * 32 + 255) / 256;
    const int zeroGrid = (NNODE + 255) / 256;

    // 1) fused K weights (rel_att folded in)
    fuse_k<<<fuseGrid, 256>>>(Wk_u, bk_u, rel_att, fWku, fbku);
    fuse_k<<<fuseGrid, 256>>>(Wk_i, bk_i, rel_att + NHEAD * 16 * 16, fWki, fbki);

    // 2) projections
    gemm128<0,0,0><<<gemmGrid, 256>>>(h_user, nullptr, fWku, fbku, nullptr, nullptr, Ku, NNODE);
    gemm128<0,0,0><<<gemmGrid, 256>>>(h_user, nullptr, Wq_u, bq_u, nullptr, nullptr, Qu, NNODE);
    gemm128<0,0,0><<<gemmGrid, 256>>>(h_user, nullptr, Wv_u, bv_u, nullptr, nullptr, Vru, NNODE);
    gemm128<0,0,0><<<gemmGrid, 256>>>(h_item, nullptr, fWki, fbki, nullptr, nullptr, Ki, NNODE);
    gemm128<0,0,0><<<gemmGrid, 256>>>(h_item, nullptr, Wq_i, bq_i, nullptr, nullptr, Qi, NNODE);
    gemm128<0,0,0><<<gemmGrid, 256>>>(h_item, nullptr, Wv_i, bv_i, nullptr, nullptr, Vri, NNODE);
    blockdiag<<<bdGrid, 256>>>(Vru, rel_msg, Vtu, NNODE);
    blockdiag<<<bdGrid, 256>>>(Vri, rel_msg + NHEAD * 256, Vti, NNODE);

    // 3) relation 0: user -buys-> item  (dst = items)
    zero_ints<<<zeroGrid, 256>>>(counts, NNODE);
    count_edges<<<edgeGrid, 256>>>(buys_dst, counts);
    scan_offsets<<<1, 1024>>>(counts, offsets, NNODE);
    zero_ints<<<zeroGrid, 256>>>(cursor, NNODE);
    scatter_edges<<<edgeGrid, 256>>>(buys_src, buys_dst, offsets, cursor, elist);
    attn_agg<<<warpGrid, 256>>>(Qi, Ku, Vtu, offsets, elist, rel_pri, rawb, lti, hti, NNODE);

    // 4) relation 1: item -rev-> user  (dst = users)
    zero_ints<<<zeroGrid, 256>>>(counts, NNODE);
    count_edges<<<edgeGrid, 256>>>(rev_dst, counts);
    scan_offsets<<<1, 1024>>>(counts, offsets, NNODE);
    zero_ints<<<zeroGrid, 256>>>(cursor, NNODE);
    scatter_edges<<<edgeGrid, 256>>>(rev_src, rev_dst, offsets, cursor, elist);
    attn_agg<<<warpGrid, 256>>>(Qu, Ki, Vti, offsets, elist, rel_pri + NHEAD, rawb, ltu, htu, NNODE);

    // 5) user update
    gemm128<1,1,0><<<gemmGrid, 256>>>(Vru, ltu, Wf, bf, nullptr, nullptr, HZ0, NNODE);
    gemm128<2,1,0><<<gemmGrid, 256>>>(Vru, htu, Wf, bf, nullptr, nullptr, HZ1, NNODE);
    gemm128<0,1,0><<<gemmGrid, 256>>>(Vru, nullptr, Wx, bx, nullptr, nullptr, XP, NNODE);
    compute_T<<<warpGrid, 256>>>(Vru, ltu, htu, HZ0, HZ1, XP, T, NNODE);
    gemm128<0,0,1><<<gemmGrid, 256>>>(T, nullptr, Wa_u, ba_u, h_user, skip + 0, out_u, NNODE);

    // 6) item update
    gemm128<1,1,0><<<gemmGrid, 256>>>(Vri, lti, Wf, bf, nullptr, nullptr, HZ0, NNODE);
    gemm128<2,1,0><<<gemmGrid, 256>>>(Vri, hti, Wf, bf, nullptr, nullptr, HZ1, NNODE);
    gemm128<0,1,0><<<gemmGrid, 256>>>(Vri, nullptr, Wx, bx, nullptr, nullptr, XP, NNODE);
    compute_T<<<warpGrid, 256>>>(Vri, lti, hti, HZ0, HZ1, XP, T, NNODE);
    gemm128<0,0,1><<<gemmGrid, 256>>>(T, nullptr, Wa_i, ba_i, h_item, skip + 1, out_i, NNODE);
}

// round 7
// speedup vs baseline: 1.1358x; 1.1358x over previous
#include <cuda_runtime.h>
#include <cuda_bf16.h>
#include <math.h>

#define NNODE 50000
#define DIM   128
#define NEDGE 400000
#define NHEAD 8

// ------------------------- device scratch (no allocs allowed) -------------------------
__device__ float g_Ku[NNODE*DIM];
__device__ float g_Ki[NNODE*DIM];
__device__ float g_Qu[NNODE*DIM];
__device__ float g_Qi[NNODE*DIM];
__device__ float g_Vru[NNODE*DIM];
__device__ float g_Vri[NNODE*DIM];
__device__ float g_Vtu[NNODE*DIM];
__device__ float g_Vti[NNODE*DIM];
__device__ float g_ltu[NNODE*DIM];
__device__ float g_htu[NNODE*DIM];
__device__ float g_lti[NNODE*DIM];
__device__ float g_hti[NNODE*DIM];
__device__ float g_HZ0[NNODE*DIM];
__device__ float g_HZ1[NNODE*DIM];
__device__ float g_XP[NNODE*DIM];
__device__ float g_T[NNODE*DIM];
__device__ float g_raw[(size_t)NEDGE*NHEAD];
__device__ int   g_counts[NNODE];
__device__ int   g_cursor[NNODE];
__device__ int   g_offsets[NNODE+1];
__device__ int   g_bsums[64];
__device__ int   g_elist[NEDGE];
__device__ float g_fWku[DIM*DIM];
__device__ float g_fbku[DIM];
__device__ float g_fWki[DIM*DIM];
__device__ float g_fbki[DIM];

// ------------------------- zero an int buffer -------------------------
__global__ void zero_ints(int* __restrict__ p, int n) {
    int i = blockIdx.x * blockDim.x + threadIdx.x;
    if (i < n) p[i] = 0;
}

// ------------------------- fused K-weight build: Wk' = Wk @ blockdiag(rel_att) -------------------------
__global__ void fuse_k(const float* __restrict__ Wk, const float* __restrict__ bk,
                       const float* __restrict__ ra, float* __restrict__ fW, float* __restrict__ fb) {
    int idx = blockIdx.x * blockDim.x + threadIdx.x;
    if (idx < DIM * DIM) {
        int j = idx >> 7, c = idx & 127;
        int h = c >> 4, k = c & 15;
        float s = 0.f;
#pragma unroll
        for (int d = 0; d < 16; d++)
            s += Wk[(j << 7) + (h << 4) + d] * ra[(h * 16 + d) * 16 + k];
        fW[idx] = s;
    } else if (idx < DIM * DIM + DIM) {
        int c = idx - DIM * DIM;
        int h = c >> 4, k = c & 15;
        float s = 0.f;
#pragma unroll
        for (int d = 0; d < 16; d++)
            s += bk[(h << 4) + d] * ra[(h * 16 + d) * 16 + k];
        fb[c] = s;
    }
}

// ------------------------- Y = X @ blockdiag(rel_msg) -------------------------
__global__ void blockdiag(const float* __restrict__ X, const float* __restrict__ RM,
                          float* __restrict__ Y, int N) {
    __shared__ float sm[NHEAD * 16 * 16];
    for (int i = threadIdx.x; i < NHEAD * 256; i += blockDim.x) sm[i] = RM[i];
    __syncthreads();
    int idx = blockIdx.x * blockDim.x + threadIdx.x;
    if (idx >= N * DIM) return;
    int c = idx & 127;
    int h = c >> 4, kk = c & 15;
    const float* xr = X + (idx & ~127) + (h << 4);
    const float* m = sm + h * 256 + kk;
    float s = 0.f;
#pragma unroll
    for (int d = 0; d < 16; d++) s += xr[d] * m[d * 16];
    Y[idx] = s;
}

// ===================== fp32 f32x2-FFMA GEMM (exact path for K/Q) =====================
__device__ __forceinline__ unsigned long long pk2(float lo, float hi) {
    unsigned long long r;
    asm("mov.b64 %0, {%1, %2};" : "=l"(r) : "f"(lo), "f"(hi));
    return r;
}
__device__ __forceinline__ void upk2(unsigned long long v, float &lo, float &hi) {
    asm("mov.b64 {%0, %1}, %2;" : "=f"(lo), "=f"(hi) : "l"(v));
}
__device__ __forceinline__ void ffma2(unsigned long long &d, unsigned long long a, unsigned long long b) {
    asm("fma.rn.f32x2 %0, %1, %2, %0;" : "+l"(d) : "l"(a), "l"(b));
}

__global__ __launch_bounds__(256) void gemm128_fp32(
    const float* __restrict__ A, const float* __restrict__ W, const float* __restrict__ bias,
    float* __restrict__ C, int N)
{
    __shared__ __align__(16) float As[32][64];   // transposed: As[k][m]
    __shared__ __align__(16) float Ws[32][128];
    const int tid = threadIdx.x;
    const int tx = tid & 31, ty = tid >> 5;
    const int rowBase = blockIdx.x * 64;

    unsigned long long acc[8][2];
#pragma unroll
    for (int r = 0; r < 8; r++) { acc[r][0] = 0ull; acc[r][1] = 0ull; }

    for (int k0 = 0; k0 < DIM; k0 += 32) {
#pragma unroll
        for (int i = 0; i < 2; i++) {
            int row = (tid >> 3) + i * 32;
            int c4 = (tid & 7) * 4;
            int grow = rowBase + row;
            float4 v = make_float4(0.f, 0.f, 0.f, 0.f);
            if (grow < N) v = *(const float4*)(A + (size_t)grow * DIM + k0 + c4);
            As[c4 + 0][row] = v.x; As[c4 + 1][row] = v.y;
            As[c4 + 2][row] = v.z; As[c4 + 3][row] = v.w;
        }
#pragma unroll
        for (int i = 0; i < 4; i++) {
            int kr = (tid >> 5) + i * 8;
            *(float4*)&Ws[kr][(tid & 31) * 4] =
                *(const float4*)(W + (size_t)(k0 + kr) * DIM + (tid & 31) * 4);
        }
        __syncthreads();
#pragma unroll
        for (int k = 0; k < 32; k++) {
            float4 a0 = *(float4*)&As[k][ty * 8];
            float4 a1 = *(float4*)&As[k][ty * 8 + 4];
            float4 w  = *(float4*)&Ws[k][tx * 4];
            unsigned long long wp0 = pk2(w.x, w.y);
            unsigned long long wp1 = pk2(w.z, w.w);
            float ar[8] = {a0.x, a0.y, a0.z, a0.w, a1.x, a1.y, a1.z, a1.w};
#pragma unroll
            for (int r = 0; r < 8; r++) {
                unsigned long long ap = pk2(ar[r], ar[r]);
                ffma2(acc[r][0], ap, wp0);
                ffma2(acc[r][1], ap, wp1);
            }
        }
        __syncthreads();
    }

    const int col = tx * 4;
    float b0 = bias[col], b1 = bias[col + 1], b2 = bias[col + 2], b3 = bias[col + 3];
#pragma unroll
    for (int r = 0; r < 8; r++) {
        int grow = rowBase + ty * 8 + r;
        if (grow < N) {
            float o0, o1, o2, o3;
            upk2(acc[r][0], o0, o1); upk2(acc[r][1], o2, o3);
            *(float4*)(C + (size_t)grow * DIM + col) =
                make_float4(o0 + b0, o1 + b1, o2 + b2, o3 + b3);
        }
    }
}

// ===================== tf32x3 tensor-core GEMM (V + update path) =====================
// MIN_: 0 -> A ; 1 -> A+A2 ; 2 -> A-A2.   ACT_: 0 none, 1 tanh.
// MOUT_: 0 plain ; 1 -> C = (..)*sigmoid(*skipp) + Dres*(1-sigmoid(*skipp))
#define BM 128
#define BK 16
#define ASTR 20
#define BSTR 136

__device__ __forceinline__ unsigned f2tf32(float f) {
    unsigned r;
    asm("cvt.rna.tf32.f32 %0, %1;" : "=r"(r) : "f"(f));
    return r;
}

__device__ __forceinline__ void mma_tf32(float* c, const unsigned* a, const unsigned* b) {
    asm volatile(
        "mma.sync.aligned.m16n8k8.row.col.f32.tf32.tf32.f32 "
        "{%0,%1,%2,%3}, {%4,%5,%6,%7}, {%8,%9}, {%0,%1,%2,%3};"
        : "+f"(c[0]), "+f"(c[1]), "+f"(c[2]), "+f"(c[3])
        : "r"(a[0]), "r"(a[1]), "r"(a[2]), "r"(a[3]), "r"(b[0]), "r"(b[1]));
}

template<int MIN_, int ACT_, int MOUT_>
__global__ __launch_bounds__(256) void gemm128_tf32(
    const float* __restrict__ A, const float* __restrict__ A2,
    const float* __restrict__ W, const float* __restrict__ bias,
    const float* __restrict__ Dres, const float* __restrict__ skipp,
    float* __restrict__ C, int N)
{
    __shared__ __align__(16) unsigned Ahs[BM * ASTR];
    __shared__ __align__(16) unsigned Als[BM * ASTR];
    __shared__ __align__(16) unsigned Bhs[BK * BSTR];
    __shared__ __align__(16) unsigned Bls[BK * BSTR];

    const int tid = threadIdx.x;
    const int lane = tid & 31;
    const int wid = tid >> 5;
    const int warp_m = (wid >> 2) * 64;
    const int warp_n = (wid & 3) * 32;
    const int rowBase = blockIdx.x * BM;

    float acc[4][4][4];
#pragma unroll
    for (int i = 0; i < 4; i++)
#pragma unroll
        for (int j = 0; j < 4; j++)
#pragma unroll
            for (int r = 0; r < 4; r++) acc[i][j][r] = 0.f;

    for (int k0 = 0; k0 < DIM; k0 += BK) {
#pragma unroll
        for (int it = 0; it < 2; it++) {
            int idx = tid + it * 256;
            int row = idx >> 2;
            int c4 = (idx & 3) * 4;
            int grow = rowBase + row;
            float4 v = make_float4(0.f, 0.f, 0.f, 0.f);
            if (grow < N) {
                v = *(const float4*)(A + (size_t)grow * DIM + k0 + c4);
                if (MIN_ == 1) {
                    float4 b = *(const float4*)(A2 + (size_t)grow * DIM + k0 + c4);
                    v.x += b.x; v.y += b.y; v.z += b.z; v.w += b.w;
                } else if (MIN_ == 2) {
                    float4 b = *(const float4*)(A2 + (size_t)grow * DIM + k0 + c4);
                    v.x -= b.x; v.y -= b.y; v.z -= b.z; v.w -= b.w;
                }
            }
            float f[4] = {v.x, v.y, v.z, v.w};
#pragma unroll
            for (int q = 0; q < 4; q++) {
                unsigned hb = f2tf32(f[q]);
                float lo = f[q] - __uint_as_float(hb);
                Ahs[row * ASTR + c4 + q] = hb;
                Als[row * ASTR + c4 + q] = f2tf32(lo);
            }
        }
#pragma unroll
        for (int it = 0; it < 2; it++) {
            int idx = tid + it * 256;
            int kr = idx >> 5;
            int c4 = (idx & 31) * 4;
            float4 v = *(const float4*)(W + (size_t)(k0 + kr) * DIM + c4);
            float f[4] = {v.x, v.y, v.z, v.w};
#pragma unroll
            for (int q = 0; q < 4; q++) {
                unsigned hb = f2tf32(f[q]);
                float lo = f[q] - __uint_as_float(hb);
                Bhs[kr * BSTR + c4 + q] = hb;
                Bls[kr * BSTR + c4 + q] = f2tf32(lo);
            }
        }
        __syncthreads();

#pragma unroll
        for (int ks = 0; ks < BK; ks += 8) {
            unsigned bh[4][2], bl[4][2];
            const int kb0 = (ks + (lane & 3)) * BSTR;
            const int kb1 = kb0 + 4 * BSTR;
            const int nb = warp_n + (lane >> 2);
#pragma unroll
            for (int j = 0; j < 4; j++) {
                int cn = nb + j * 8;
                bh[j][0] = Bhs[kb0 + cn]; bh[j][1] = Bhs[kb1 + cn];
                bl[j][0] = Bls[kb0 + cn]; bl[j][1] = Bls[kb1 + cn];
            }
#pragma unroll
            for (int i = 0; i < 4; i++) {
                int r0 = (warp_m + i * 16 + (lane >> 2)) * ASTR;
                int r1 = r0 + 8 * ASTR;
                int c0 = ks + (lane & 3);
                unsigned ah[4], al[4];
                ah[0] = Ahs[r0 + c0]; ah[1] = Ahs[r1 + c0];
                ah[2] = Ahs[r0 + c0 + 4]; ah[3] = Ahs[r1 + c0 + 4];
                al[0] = Als[r0 + c0]; al[1] = Als[r1 + c0];
                al[2] = Als[r0 + c0 + 4]; al[3] = Als[r1 + c0 + 4];
#pragma unroll
                for (int j = 0; j < 4; j++) {
                    mma_tf32(acc[i][j], ah, bh[j]);
                    mma_tf32(acc[i][j], ah, bl[j]);
                    mma_tf32(acc[i][j], al, bh[j]);
                }
            }
        }
        __syncthreads();
    }

    float alpha = 1.f, onem = 0.f;
    if (MOUT_ == 1) {
        float s = *skipp;
        alpha = 1.f / (1.f + __expf(-s));
        onem = 1.f - alpha;
    }
    const int g = lane >> 2, t = lane & 3;
#pragma unroll
    for (int i = 0; i < 4; i++) {
        int r0 = rowBase + warp_m + i * 16 + g;
        int r1 = r0 + 8;
#pragma unroll
        for (int j = 0; j < 4; j++) {
            int col = warp_n + j * 8 + t * 2;
            float b0 = bias[col], b1 = bias[col + 1];
            float o0 = acc[i][j][0] + b0, o1 = acc[i][j][1] + b1;
            float o2 = acc[i][j][2] + b0, o3 = acc[i][j][3] + b1;
            if (ACT_ == 1) { o0 = tanhf(o0); o1 = tanhf(o1); o2 = tanhf(o2); o3 = tanhf(o3); }
            if (r0 < N) {
                if (MOUT_ == 1) {
                    float2 dr = *(const float2*)(Dres + (size_t)r0 * DIM + col);
                    o0 = o0 * alpha + dr.x * onem;
                    o1 = o1 * alpha + dr.y * onem;
                }
                float2 ov; ov.x = o0; ov.y = o1;
                *(float2*)(C + (size_t)r0 * DIM + col) = ov;
            }
            if (r1 < N) {
                if (MOUT_ == 1) {
                    float2 dr = *(const float2*)(Dres + (size_t)r1 * DIM + col);
                    o2 = o2 * alpha + dr.x * onem;
                    o3 = o3 * alpha + dr.y * onem;
                }
                float2 ov; ov.x = o2; ov.y = o3;
                *(float2*)(C + (size_t)r1 * DIM + col) = ov;
            }
        }
    }
}

// ------------------------- CSR build -------------------------
__global__ void count_edges(const int* __restrict__ dst, int* __restrict__ counts) {
    int e = blockIdx.x * blockDim.x + threadIdx.x;
    if (e < NEDGE) atomicAdd(&counts[dst[e]], 1);
}

__global__ void scan_blocks(const int* __restrict__ counts, int* __restrict__ offsets,
                            int* __restrict__ bsums, int n) {
    __shared__ int sh[1024];
    int tid = threadIdx.x;
    int i = blockIdx.x * 1024 + tid;
    int v = (i < n) ? counts[i] : 0;
    sh[tid] = v;
    __syncthreads();
    for (int off = 1; off < 1024; off <<= 1) {
        int t = (tid >= off) ? sh[tid - off] : 0;
        __syncthreads();
        sh[tid] += t;
        __syncthreads();
    }
    if (i < n) offsets[i + 1] = sh[tid];
    if (tid == 1023) bsums[blockIdx.x] = sh[1023];
}

__global__ void scan_sums(int* __restrict__ bsums, int nb) {
    if (threadIdx.x == 0) {
        int acc = 0;
        for (int b = 0; b < nb; b++) { int t = bsums[b]; bsums[b] = acc; acc += t; }
    }
}

__global__ void add_carry(int* __restrict__ offsets, const int* __restrict__ bsums, int n) {
    int i = blockIdx.x * 1024 + threadIdx.x;
    if (i < n) offsets[i + 1] += bsums[blockIdx.x];
    if (i == 0) offsets[0] = 0;
}

__global__ void scatter_edges(const int* __restrict__ src, const int* __restrict__ dst,
                              const int* __restrict__ offsets, int* __restrict__ cursor,
                              int* __restrict__ elist) {
    int e = blockIdx.x * blockDim.x + threadIdx.x;
    if (e < NEDGE) {
        int d = dst[e];
        int p = atomicAdd(&cursor[d], 1);
        elist[offsets[d] + p] = src[e];
    }
}

// ------------------------- per-dst edge softmax (both branches) + aggregation -------------------------
__global__ void attn_agg(const float* __restrict__ Q, const float* __restrict__ K,
                         const float* __restrict__ V,
                         const int* __restrict__ offsets, const int* __restrict__ elist,
                         const float* __restrict__ pri,
                         float* __restrict__ rawb,
                         float* __restrict__ lt_out, float* __restrict__ ht_out, int Ndst)
{
    int warp = (blockIdx.x * blockDim.x + threadIdx.x) >> 5;
    int lane = threadIdx.x & 31;
    if (warp >= Ndst) return;
    const int beg = offsets[warp], end = offsets[warp + 1];
    const int h = lane >> 2;
    const float scale = pri[h] * 0.25f;
    float4 q = *(const float4*)(Q + (size_t)warp * DIM + lane * 4);

    float m_lf = __int_as_float(0xff800000);
    float m_hf = m_lf;
    for (int e = beg; e < end; e++) {
        int s = elist[e];
        float4 kv = *(const float4*)(K + (size_t)s * DIM + lane * 4);
        float p = q.x * kv.x + q.y * kv.y + q.z * kv.z + q.w * kv.w;
        p += __shfl_xor_sync(0xffffffffu, p, 1);
        p += __shfl_xor_sync(0xffffffffu, p, 2);
        float raw = p * scale;
        if ((lane & 3) == 0) rawb[(size_t)e * NHEAD + h] = raw;
        m_lf = fmaxf(m_lf, raw);
        m_hf = fmaxf(m_hf, 1.0f / (raw + 1e-6f));
    }
    float z_lf = 0.f, z_hf = 0.f;
    float4 alt = make_float4(0.f, 0.f, 0.f, 0.f);
    float4 aht = make_float4(0.f, 0.f, 0.f, 0.f);
    for (int e = beg; e < end; e++) {
        int s = elist[e];
        float rl = 0.f;
        if ((lane & 3) == 0) rl = rawb[(size_t)e * NHEAD + h];
        float raw = __shfl_sync(0xffffffffu, rl, lane & ~3);
        float elf = __expf(raw - m_lf);
        float ehf = __expf(1.0f / (raw + 1e-6f) - m_hf);
        z_lf += elf; z_hf += ehf;
        float4 v = *(const float4*)(V + (size_t)s * DIM + lane * 4);
        alt.x += v.x * elf; alt.y += v.y * elf; alt.z += v.z * elf; alt.w += v.w * elf;
        aht.x += v.x * ehf; aht.y += v.y * ehf; aht.z += v.z * ehf; aht.w += v.w * ehf;
    }
    float izl = (end > beg) ? 1.0f / z_lf : 0.f;
    float izh = (end > beg) ? 1.0f / z_hf : 0.f;
    *(float4*)(lt_out + (size_t)warp * DIM + lane * 4) =
        make_float4(alt.x * izl, alt.y * izl, alt.z * izl, alt.w * izl);
    *(float4*)(ht_out + (size_t)warp * DIM + lane * 4) =
        make_float4(aht.x * izh, aht.y * izh, aht.z * izh, aht.w * izh);
}

// ------------------------- gate scores + blended T -------------------------
__global__ void compute_T(const float* __restrict__ Vr, const float* __restrict__ lta,
                          const float* __restrict__ hta, const float* __restrict__ HZ0,
                          const float* __restrict__ HZ1, const float* __restrict__ XP,
                          float* __restrict__ T, int N)
{
    int warp = (blockIdx.x * blockDim.x + threadIdx.x) >> 5;
    int lane = threadIdx.x & 31;
    if (warp >= N) return;
    size_t base = (size_t)warp * DIM + lane * 4;
    float4 hz0 = *(const float4*)(HZ0 + base);
    float4 hz1 = *(const float4*)(HZ1 + base);
    float4 xp  = *(const float4*)(XP + base);
    float s0 = hz0.x * xp.x + hz0.y * xp.y + hz0.z * xp.z + hz0.w * xp.w;
    float s1 = hz1.x * xp.x + hz1.y * xp.y + hz1.z * xp.z + hz1.w * xp.w;
#pragma unroll
    for (int o = 16; o > 0; o >>= 1) {
        s0 += __shfl_xor_sync(0xffffffffu, s0, o);
        s1 += __shfl_xor_sync(0xffffffffu, s1, o);
    }
    float m = fmaxf(s0, s1);
    float e0 = __expf(s0 - m), e1 = __expf(s1 - m);
    float inv = 1.0f / (e0 + e1);
    float sc0 = e0 * inv, sc1 = e1 * inv;
    float4 ori = *(const float4*)(Vr + base);
    float4 la  = *(const float4*)(lta + base);
    float4 ha  = *(const float4*)(hta + base);
    float4 t;
    t.x = (ori.x + la.x) * sc0 + (ori.x - ha.x) * sc1;
    t.y = (ori.y + la.y) * sc0 + (ori.y - ha.y) * sc1;
    t.z = (ori.z + la.z) * sc0 + (ori.z - ha.z) * sc1;
    t.w = (ori.w + la.w) * sc0 + (ori.w - ha.w) * sc1;
    *(float4*)(T + base) = t;
}

// ------------------------- launch -------------------------
extern "C" void kernel_launch(void* const* d_in, const int* in_sizes, int n_in,
                              void* d_out, int out_size) {
    const float* h_user = (const float*)d_in[0];
    const float* h_item = (const float*)d_in[1];
    const int* buys_src = (const int*)d_in[2];
    const int* buys_dst = (const int*)d_in[3];
    const int* rev_src  = (const int*)d_in[4];
    const int* rev_dst  = (const int*)d_in[5];
    const float* Wk_u = (const float*)d_in[6];  const float* bk_u = (const float*)d_in[7];
    const float* Wk_i = (const float*)d_in[8];  const float* bk_i = (const float*)d_in[9];
    const float* Wq_u = (const float*)d_in[10]; const float* bq_u = (const float*)d_in[11];
    const float* Wq_i = (const float*)d_in[12]; const float* bq_i = (const float*)d_in[13];
    const float* Wv_u = (const float*)d_in[14]; const float* bv_u = (const float*)d_in[15];
    const float* Wv_i = (const float*)d_in[16]; const float* bv_i = (const float*)d_in[17];
    const float* Wa_u = (const float*)d_in[18]; const float* ba_u = (const float*)d_in[19];
    const float* Wa_i = (const float*)d_in[20]; const float* ba_i = (const float*)d_in[21];
    const float* Wf = (const float*)d_in[22];   const float* bf = (const float*)d_in[23];
    const float* Wx = (const float*)d_in[24];   const float* bx = (const float*)d_in[25];
    const float* rel_pri = (const float*)d_in[26];
    const float* rel_att = (const float*)d_in[27];
    const float* rel_msg = (const float*)d_in[28];
    const float* skip = (const float*)d_in[29];
    float* out_u = (float*)d_out;
    float* out_i = (float*)d_out + (size_t)NNODE * DIM;

    float *Ku, *Ki, *Qu, *Qi, *Vru, *Vri, *Vtu, *Vti;
    float *ltu, *htu, *lti, *hti, *HZ0, *HZ1, *XP, *T, *rawb;
    float *fWku, *fbku, *fWki, *fbki;
    int *counts, *cursor, *offsets, *elist, *bsums;
#define SYM(p, s) cudaGetSymbolAddress((void**)&p, s)
    SYM(Ku, g_Ku); SYM(Ki, g_Ki); SYM(Qu, g_Qu); SYM(Qi, g_Qi);
    SYM(Vru, g_Vru); SYM(Vri, g_Vri); SYM(Vtu, g_Vtu); SYM(Vti, g_Vti);
    SYM(ltu, g_ltu); SYM(htu, g_htu); SYM(lti, g_lti); SYM(hti, g_hti);
    SYM(HZ0, g_HZ0); SYM(HZ1, g_HZ1); SYM(XP, g_XP); SYM(T, g_T); SYM(rawb, g_raw);
    SYM(counts, g_counts); SYM(cursor, g_cursor); SYM(offsets, g_offsets); SYM(elist, g_elist);
    SYM(bsums, g_bsums);
    SYM(fWku, g_fWku); SYM(fbku, g_fbku); SYM(fWki, g_fWki); SYM(fbki, g_fbki);
#undef SYM

    const int gemmGridTF = (NNODE + BM - 1) / BM;
    const int gemmGridFP = (NNODE + 63) / 64;
    const int fuseGrid = (DIM * DIM + DIM + 255) / 256;
    const int bdGrid = (NNODE * DIM + 255) / 256;
    const int edgeGrid = (NEDGE + 255) / 256;
    const int warpGrid = (NNODE * 32 + 255) / 256;
    const int zeroGrid = (NNODE + 255) / 256;
    const int scanBlocks = (NNODE + 1023) / 1024;

    // 1) fused K weights
    fuse_k<<<fuseGrid, 256>>>(Wk_u, bk_u, rel_att, fWku, fbku);
    fuse_k<<<fuseGrid, 256>>>(Wk_i, bk_i, rel_att + NHEAD * 16 * 16, fWki, fbki);

    // 2) projections: K/Q in exact fp32 (pole-sensitive raw scores), V in tf32x3
    gemm128_fp32<<<gemmGridFP, 256>>>(h_user, fWku, fbku, Ku, NNODE);
    gemm128_fp32<<<gemmGridFP, 256>>>(h_user, Wq_u, bq_u, Qu, NNODE);
    gemm128_fp32<<<gemmGridFP, 256>>>(h_item, fWki, fbki, Ki, NNODE);
    gemm128_fp32<<<gemmGridFP, 256>>>(h_item, Wq_i, bq_i, Qi, NNODE);
    gemm128_tf32<0,0,0><<<gemmGridTF, 256>>>(h_user, nullptr, Wv_u, bv_u, nullptr, nullptr, Vru, NNODE);
    gemm128_tf32<0,0,0><<<gemmGridTF, 256>>>(h_item, nullptr, Wv_i, bv_i, nullptr, nullptr, Vri, NNODE);
    blockdiag<<<bdGrid, 256>>>(Vru, rel_msg, Vtu, NNODE);
    blockdiag<<<bdGrid, 256>>>(Vri, rel_msg + NHEAD * 256, Vti, NNODE);

    // 3) relation 0: user -buys-> item  (dst = items)
    zero_ints<<<zeroGrid, 256>>>(counts, NNODE);
    count_edges<<<edgeGrid, 256>>>(buys_dst, counts);
    scan_blocks<<<scanBlocks, 1024>>>(counts, offsets, bsums, NNODE);
    scan_sums<<<1, 32>>>(bsums, scanBlocks);
    add_carry<<<scanBlocks, 1024>>>(offsets, bsums, NNODE);
    zero_ints<<<zeroGrid, 256>>>(cursor, NNODE);
    scatter_edges<<<edgeGrid, 256>>>(buys_src, buys_dst, offsets, cursor, elist);
    attn_agg<<<warpGrid, 256>>>(Qi, Ku, Vtu, offsets, elist, rel_pri, rawb, lti, hti, NNODE);

    // 4) relation 1: item -rev-> user  (dst = users)
    zero_ints<<<zeroGrid, 256>>>(counts, NNODE);
    count_edges<<<edgeGrid, 256>>>(rev_dst, counts);
    scan_blocks<<<scanBlocks, 1024>>>(counts, offsets, bsums, NNODE);
    scan_sums<<<1, 32>>>(bsums, scanBlocks);
    add_carry<<<scanBlocks, 1024>>>(offsets, bsums, NNODE);
    zero_ints<<<zeroGrid, 256>>>(cursor, NNODE);
    scatter_edges<<<edgeGrid, 256>>>(rev_src, rev_dst, offsets, cursor, elist);
    attn_agg<<<warpGrid, 256>>>(Qu, Ki, Vti, offsets, elist, rel_pri + NHEAD, rawb, ltu, htu, NNODE);

    // 5) user update
    gemm128_tf32<1,1,0><<<gemmGridTF, 256>>>(Vru, ltu, Wf, bf, nullptr, nullptr, HZ0, NNODE);
    gemm128_tf32<2,1,0><<<gemmGridTF, 256>>>(Vru, htu, Wf, bf, nullptr, nullptr, HZ1, NNODE);
    gemm128_tf32<0,1,0><<<gemmGridTF, 256>>>(Vru, nullptr, Wx, bx, nullptr, nullptr, XP, NNODE);
    compute_T<<<warpGrid, 256>>>(Vru, ltu, htu, HZ0, HZ1, XP, T, NNODE);
    gemm128_tf32<0,0,1><<<gemmGridTF, 256>>>(T, nullptr, Wa_u, ba_u, h_user, skip + 0, out_u, NNODE);

    // 6) item update
    gemm128_tf32<1,1,0><<<gemmGridTF, 256>>>(Vri, lti, Wf, bf, nullptr, nullptr, HZ0, NNODE);
    gemm128_tf32<2,1,0><<<gemmGridTF, 256>>>(Vri, hti, Wf, bf, nullptr, nullptr, HZ1, NNODE);
    gemm128_tf32<0,1,0><<<gemmGridTF, 256>>>(Vri, nullptr, Wx, bx, nullptr, nullptr, XP, NNODE);
    compute_T<<<warpGrid, 256>>>(Vri, lti, hti, HZ0, HZ1, XP, T, NNODE);
    gemm128_tf32<0,0,1><<<gemmGridTF, 256>>>(T, nullptr, Wa_i, ba_i, h_item, skip + 1, out_i, NNODE);
}

// round 8
// speedup vs baseline: 1.3888x; 1.2228x over previous
#include <cuda_runtime.h>
#include <cuda_bf16.h>
#include <math.h>

#define NNODE 50000
#define DIM   128
#define NEDGE 400000
#define NHEAD 8

// ------------------------- device scratch (no allocs allowed) -------------------------
__device__ float g_Ku[NNODE*DIM];
__device__ float g_Ki[NNODE*DIM];
__device__ float g_Qu[NNODE*DIM];
__device__ float g_Qi[NNODE*DIM];
__device__ float g_Vru[NNODE*DIM];
__device__ float g_Vri[NNODE*DIM];
__device__ float g_Vtu[NNODE*DIM];
__device__ float g_Vti[NNODE*DIM];
__device__ float g_ltu[NNODE*DIM];
__device__ float g_htu[NNODE*DIM];
__device__ float g_lti[NNODE*DIM];
__device__ float g_hti[NNODE*DIM];
__device__ float g_HZ0[NNODE*DIM];
__device__ float g_HZ1[NNODE*DIM];
__device__ float g_XP[NNODE*DIM];
__device__ float g_T[NNODE*DIM];
__device__ float g_raw[(size_t)NEDGE*NHEAD];
__device__ int   g_counts[NNODE];
__device__ int   g_cursor[NNODE];
__device__ int   g_offsets[NNODE+1];
__device__ int   g_bsums[64];
__device__ int   g_elist[NEDGE];
__device__ float g_fWku[DIM*DIM];
__device__ float g_fbku[DIM];
__device__ float g_fWki[DIM*DIM];
__device__ float g_fbki[DIM];
__device__ float g_fWvu[DIM*DIM];
__device__ float g_fbvu[DIM];
__device__ float g_fWvi[DIM*DIM];
__device__ float g_fbvi[DIM];

// ------------------------- zero an int buffer -------------------------
__global__ void zero_ints(int* __restrict__ p, int n) {
    int i = blockIdx.x * blockDim.x + threadIdx.x;
    if (i < n) p[i] = 0;
}

// ------------------------- fused weight build: W' = W @ blockdiag(R), b' = b @ blockdiag(R) ----
__global__ void fuse_k(const float* __restrict__ Wk, const float* __restrict__ bk,
                       const float* __restrict__ ra, float* __restrict__ fW, float* __restrict__ fb) {
    int idx = blockIdx.x * blockDim.x + threadIdx.x;
    if (idx < DIM * DIM) {
        int j = idx >> 7, c = idx & 127;
        int h = c >> 4, k = c & 15;
        float s = 0.f;
#pragma unroll
        for (int d = 0; d < 16; d++)
            s += Wk[(j << 7) + (h << 4) + d] * ra[(h * 16 + d) * 16 + k];
        fW[idx] = s;
    } else if (idx < DIM * DIM + DIM) {
        int c = idx - DIM * DIM;
        int h = c >> 4, k = c & 15;
        float s = 0.f;
#pragma unroll
        for (int d = 0; d < 16; d++)
            s += bk[(h << 4) + d] * ra[(h * 16 + d) * 16 + k];
        fb[c] = s;
    }
}

// ===================== fp32 f32x2-FFMA GEMM (exact path for K/Q) =====================
__device__ __forceinline__ unsigned long long pk2(float lo, float hi) {
    unsigned long long r;
    asm("mov.b64 %0, {%1, %2};" : "=l"(r) : "f"(lo), "f"(hi));
    return r;
}
__device__ __forceinline__ void upk2(unsigned long long v, float &lo, float &hi) {
    asm("mov.b64 {%0, %1}, %2;" : "=f"(lo), "=f"(hi) : "l"(v));
}
__device__ __forceinline__ void ffma2(unsigned long long &d, unsigned long long a, unsigned long long b) {
    asm("fma.rn.f32x2 %0, %1, %2, %0;" : "+l"(d) : "l"(a), "l"(b));
}

__global__ __launch_bounds__(256) void gemm128_fp32(
    const float* __restrict__ A, const float* __restrict__ W, const float* __restrict__ bias,
    float* __restrict__ C, int N)
{
    __shared__ __align__(16) float As[32][64];   // transposed: As[k][m]
    __shared__ __align__(16) float Ws[32][128];
    const int tid = threadIdx.x;
    const int tx = tid & 31, ty = tid >> 5;
    const int rowBase = blockIdx.x * 64;

    unsigned long long acc[8][2];
#pragma unroll
    for (int r = 0; r < 8; r++) { acc[r][0] = 0ull; acc[r][1] = 0ull; }

    for (int k0 = 0; k0 < DIM; k0 += 32) {
#pragma unroll
        for (int i = 0; i < 2; i++) {
            int row = (tid >> 3) + i * 32;
            int c4 = (tid & 7) * 4;
            int grow = rowBase + row;
            float4 v = make_float4(0.f, 0.f, 0.f, 0.f);
            if (grow < N) v = *(const float4*)(A + (size_t)grow * DIM + k0 + c4);
            As[c4 + 0][row] = v.x; As[c4 + 1][row] = v.y;
            As[c4 + 2][row] = v.z; As[c4 + 3][row] = v.w;
        }
#pragma unroll
        for (int i = 0; i < 4; i++) {
            int kr = (tid >> 5) + i * 8;
            *(float4*)&Ws[kr][(tid & 31) * 4] =
                *(const float4*)(W + (size_t)(k0 + kr) * DIM + (tid & 31) * 4);
        }
        __syncthreads();
#pragma unroll
        for (int k = 0; k < 32; k++) {
            float4 a0 = *(float4*)&As[k][ty * 8];
            float4 a1 = *(float4*)&As[k][ty * 8 + 4];
            float4 w  = *(float4*)&Ws[k][tx * 4];
            unsigned long long wp0 = pk2(w.x, w.y);
            unsigned long long wp1 = pk2(w.z, w.w);
            float ar[8] = {a0.x, a0.y, a0.z, a0.w, a1.x, a1.y, a1.z, a1.w};
#pragma unroll
            for (int r = 0; r < 8; r++) {
                unsigned long long ap = pk2(ar[r], ar[r]);
                ffma2(acc[r][0], ap, wp0);
                ffma2(acc[r][1], ap, wp1);
            }
        }
        __syncthreads();
    }

    const int col = tx * 4;
    float b0 = bias[col], b1 = bias[col + 1], b2 = bias[col + 2], b3 = bias[col + 3];
#pragma unroll
    for (int r = 0; r < 8; r++) {
        int grow = rowBase + ty * 8 + r;
        if (grow < N) {
            float o0, o1, o2, o3;
            upk2(acc[r][0], o0, o1); upk2(acc[r][1], o2, o3);
            *(float4*)(C + (size_t)grow * DIM + col) =
                make_float4(o0 + b0, o1 + b1, o2 + b2, o3 + b3);
        }
    }
}

// ===================== bf16x3 tensor-core GEMM (V + update path) =====================
// C[N,128] = op(A,A2) @ W + bias, fp32 in/out, bf16 hi/lo split (3 MMA passes).
// MIN_: 0 -> A ; 1 -> A+A2 ; 2 -> A-A2.   ACT_: 0 none, 1 tanh.
// MOUT_: 0 plain ; 1 -> C = (..)*sigmoid(*skipp) + Dres*(1-sigmoid(*skipp))
#define BM 128
#define BK 32
#define APAD 40    // A smem row stride (elems); 80B, 16B-aligned rows
#define BPAD 136   // B smem row stride (elems); 272B

__device__ __forceinline__ void mma_bf16(float* c, const unsigned* a, const unsigned* b) {
    asm volatile(
        "mma.sync.aligned.m16n8k16.row.col.f32.bf16.bf16.f32 "
        "{%0,%1,%2,%3}, {%4,%5,%6,%7}, {%8,%9}, {%0,%1,%2,%3};"
        : "+f"(c[0]), "+f"(c[1]), "+f"(c[2]), "+f"(c[3])
        : "r"(a[0]), "r"(a[1]), "r"(a[2]), "r"(a[3]), "r"(b[0]), "r"(b[1]));
}

template<int MIN_, int ACT_, int MOUT_>
__global__ __launch_bounds__(256) void gemm128_bf16(
    const float* __restrict__ A, const float* __restrict__ A2,
    const float* __restrict__ W, const float* __restrict__ bias,
    const float* __restrict__ Dres, const float* __restrict__ skipp,
    float* __restrict__ C, int N)
{
    __shared__ __align__(16) __nv_bfloat16 Ah[BM * APAD];
    __shared__ __align__(16) __nv_bfloat16 Al[BM * APAD];
    __shared__ __align__(16) __nv_bfloat16 Bh[BK * BPAD];
    __shared__ __align__(16) __nv_bfloat16 Bl[BK * BPAD];

    const int tid = threadIdx.x;
    const int lane = tid & 31;
    const int wid = tid >> 5;
    const int warp_m = (wid >> 2) * 64;
    const int warp_n = (wid & 3) * 32;
    const int rowBase = blockIdx.x * BM;

    float acc[4][4][4];
#pragma unroll
    for (int i = 0; i < 4; i++)
#pragma unroll
        for (int j = 0; j < 4; j++)
#pragma unroll
            for (int r = 0; r < 4; r++) acc[i][j][r] = 0.f;

    for (int k0 = 0; k0 < DIM; k0 += BK) {
#pragma unroll
        for (int it = 0; it < 4; it++) {
            int idx = tid + it * 256;
            int row = idx >> 3;
            int c4 = (idx & 7) * 4;
            int grow = rowBase + row;
            float4 v = make_float4(0.f, 0.f, 0.f, 0.f);
            if (grow < N) {
                v = *(const float4*)(A + (size_t)grow * DIM + k0 + c4);
                if (MIN_ == 1) {
                    float4 b = *(const float4*)(A2 + (size_t)grow * DIM + k0 + c4);
                    v.x += b.x; v.y += b.y; v.z += b.z; v.w += b.w;
                } else if (MIN_ == 2) {
                    float4 b = *(const float4*)(A2 + (size_t)grow * DIM + k0 + c4);
                    v.x -= b.x; v.y -= b.y; v.z -= b.z; v.w -= b.w;
                }
            }
            float f[4] = {v.x, v.y, v.z, v.w};
            __nv_bfloat16 h[4], l[4];
#pragma unroll
            for (int q = 0; q < 4; q++) {
                h[q] = __float2bfloat16(f[q]);
                l[q] = __float2bfloat16(f[q] - __bfloat162float(h[q]));
            }
            __nv_bfloat162 p;
            p.x = h[0]; p.y = h[1]; *(__nv_bfloat162*)&Ah[row * APAD + c4] = p;
            p.x = h[2]; p.y = h[3]; *(__nv_bfloat162*)&Ah[row * APAD + c4 + 2] = p;
            p.x = l[0]; p.y = l[1]; *(__nv_bfloat162*)&Al[row * APAD + c4] = p;
            p.x = l[2]; p.y = l[3]; *(__nv_bfloat162*)&Al[row * APAD + c4 + 2] = p;
        }
#pragma unroll
        for (int it = 0; it < 4; it++) {
            int idx = tid + it * 256;
            int kr = idx >> 5;
            int c4 = (idx & 31) * 4;
            float4 v = *(const float4*)(W + (size_t)(k0 + kr) * DIM + c4);
            float f[4] = {v.x, v.y, v.z, v.w};
            __nv_bfloat16 h[4], l[4];
#pragma unroll
            for (int q = 0; q < 4; q++) {
                h[q] = __float2bfloat16(f[q]);
                l[q] = __float2bfloat16(f[q] - __bfloat162float(h[q]));
            }
            __nv_bfloat162 p;
            p.x = h[0]; p.y = h[1]; *(__nv_bfloat162*)&Bh[kr * BPAD + c4] = p;
            p.x = h[2]; p.y = h[3]; *(__nv_bfloat162*)&Bh[kr * BPAD + c4 + 2] = p;
            p.x = l[0]; p.y = l[1]; *(__nv_bfloat162*)&Bl[kr * BPAD + c4] = p;
            p.x = l[2]; p.y = l[3]; *(__nv_bfloat162*)&Bl[kr * BPAD + c4 + 2] = p;
        }
        __syncthreads();

#pragma unroll
        for (int ks = 0; ks < BK; ks += 16) {
            unsigned bh[4][2], bl[4][2];
#pragma unroll
            for (int j = 0; j < 4; j++) {
                int r = ks + (lane & 15);
                int cc = warp_n + j * 8;
                unsigned ab = (unsigned)__cvta_generic_to_shared(&Bh[r * BPAD + cc]);
                asm volatile("ldmatrix.sync.aligned.m8n8.x2.trans.shared.b16 {%0,%1}, [%2];"
                             : "=r"(bh[j][0]), "=r"(bh[j][1]) : "r"(ab));
                unsigned abl = (unsigned)__cvta_generic_to_shared(&Bl[r * BPAD + cc]);
                asm volatile("ldmatrix.sync.aligned.m8n8.x2.trans.shared.b16 {%0,%1}, [%2];"
                             : "=r"(bl[j][0]), "=r"(bl[j][1]) : "r"(abl));
            }
#pragma unroll
            for (int i = 0; i < 4; i++) {
                int r = warp_m + i * 16 + (lane & 15);
                int cc = ks + (lane >> 4) * 8;
                unsigned ah[4], al[4];
                unsigned aa = (unsigned)__cvta_generic_to_shared(&Ah[r * APAD + cc]);
                asm volatile("ldmatrix.sync.aligned.m8n8.x4.shared.b16 {%0,%1,%2,%3}, [%4];"
                             : "=r"(ah[0]), "=r"(ah[1]), "=r"(ah[2]), "=r"(ah[3]) : "r"(aa));
                unsigned aal = (unsigned)__cvta_generic_to_shared(&Al[r * APAD + cc]);
                asm volatile("ldmatrix.sync.aligned.m8n8.x4.shared.b16 {%0,%1,%2,%3}, [%4];"
                             : "=r"(al[0]), "=r"(al[1]), "=r"(al[2]), "=r"(al[3]) : "r"(aal));
#pragma unroll
                for (int j = 0; j < 4; j++) {
                    mma_bf16(acc[i][j], ah, bh[j]);
                    mma_bf16(acc[i][j], ah, bl[j]);
                    mma_bf16(acc[i][j], al, bh[j]);
                }
            }
        }
        __syncthreads();
    }

    float alpha = 1.f, onem = 0.f;
    if (MOUT_ == 1) {
        float s = *skipp;
        alpha = 1.f / (1.f + __expf(-s));
        onem = 1.f - alpha;
    }
    const int g = lane >> 2, t = lane & 3;
#pragma unroll
    for (int i = 0; i < 4; i++) {
        int r0 = rowBase + warp_m + i * 16 + g;
        int r1 = r0 + 8;
#pragma unroll
        for (int j = 0; j < 4; j++) {
            int col = warp_n + j * 8 + t * 2;
            float b0 = bias[col], b1 = bias[col + 1];
            float o0 = acc[i][j][0] + b0, o1 = acc[i][j][1] + b1;
            float o2 = acc[i][j][2] + b0, o3 = acc[i][j][3] + b1;
            if (ACT_ == 1) { o0 = tanhf(o0); o1 = tanhf(o1); o2 = tanhf(o2); o3 = tanhf(o3); }
            if (r0 < N) {
                if (MOUT_ == 1) {
                    float2 dr = *(const float2*)(Dres + (size_t)r0 * DIM + col);
                    o0 = o0 * alpha + dr.x * onem;
                    o1 = o1 * alpha + dr.y * onem;
                }
                float2 ov; ov.x = o0; ov.y = o1;
                *(float2*)(C + (size_t)r0 * DIM + col) = ov;
            }
            if (r1 < N) {
                if (MOUT_ == 1) {
                    float2 dr = *(const float2*)(Dres + (size_t)r1 * DIM + col);
                    o2 = o2 * alpha + dr.x * onem;
                    o3 = o3 * alpha + dr.y * onem;
                }
                float2 ov; ov.x = o2; ov.y = o3;
                *(float2*)(C + (size_t)r1 * DIM + col) = ov;
            }
        }
    }
}

// ------------------------- CSR build -------------------------
__global__ void count_edges(const int* __restrict__ dst, int* __restrict__ counts) {
    int e = blockIdx.x * blockDim.x + threadIdx.x;
    if (e < NEDGE) atomicAdd(&counts[dst[e]], 1);
}

__global__ void scan_blocks(const int* __restrict__ counts, int* __restrict__ offsets,
                            int* __restrict__ bsums, int n) {
    __shared__ int sh[1024];
    int tid = threadIdx.x;
    int i = blockIdx.x * 1024 + tid;
    int v = (i < n) ? counts[i] : 0;
    sh[tid] = v;
    __syncthreads();
    for (int off = 1; off < 1024; off <<= 1) {
        int t = (tid >= off) ? sh[tid - off] : 0;
        __syncthreads();
        sh[tid] += t;
        __syncthreads();
    }
    if (i < n) offsets[i + 1] = sh[tid];
    if (tid == 1023) bsums[blockIdx.x] = sh[1023];
}

// parallel exclusive scan of <=64 block sums
__global__ void scan_sums(int* __restrict__ bsums, int nb) {
    __shared__ int sh[64];
    int tid = threadIdx.x;
    int v = (tid < nb) ? bsums[tid] : 0;
    sh[tid] = v;
    __syncthreads();
    for (int off = 1; off < 64; off <<= 1) {
        int t = (tid >= off) ? sh[tid - off] : 0;
        __syncthreads();
        sh[tid] += t;
        __syncthreads();
    }
    if (tid < nb) bsums[tid] = sh[tid] - v;   // exclusive
}

// add carries + zero cursor (fused)
__global__ void add_carry(int* __restrict__ offsets, const int* __restrict__ bsums,
                          int* __restrict__ cursor, int n) {
    int i = blockIdx.x * 1024 + threadIdx.x;
    if (i < n) {
        offsets[i + 1] += bsums[blockIdx.x];
        cursor[i] = 0;
    }
    if (i == 0) offsets[0] = 0;
}

__global__ void scatter_edges(const int* __restrict__ src, const int* __restrict__ dst,
                              const int* __restrict__ offsets, int* __restrict__ cursor,
                              int* __restrict__ elist) {
    int e = blockIdx.x * blockDim.x + threadIdx.x;
    if (e < NEDGE) {
        int d = dst[e];
        int p = atomicAdd(&cursor[d], 1);
        elist[offsets[d] + p] = src[e];
    }
}

// ------------------------- per-dst edge softmax (both branches) + aggregation -------------------------
__global__ void attn_agg(const float* __restrict__ Q, const float* __restrict__ K,
                         const float* __restrict__ V,
                         const int* __restrict__ offsets, const int* __restrict__ elist,
                         const float* __restrict__ pri,
                         float* __restrict__ rawb,
                         float* __restrict__ lt_out, float* __restrict__ ht_out, int Ndst)
{
    int warp = (blockIdx.x * blockDim.x + threadIdx.x) >> 5;
    int lane = threadIdx.x & 31;
    if (warp >= Ndst) return;
    const int beg = offsets[warp], end = offsets[warp + 1];
    const int h = lane >> 2;
    const float scale = pri[h] * 0.25f;
    float4 q = *(const float4*)(Q + (size_t)warp * DIM + lane * 4);

    float m_lf = __int_as_float(0xff800000);
    float m_hf = m_lf;
    for (int e = beg; e < end; e++) {
        int s = elist[e];
        float4 kv = *(const float4*)(K + (size_t)s * DIM + lane * 4);
        float p = q.x * kv.x + q.y * kv.y + q.z * kv.z + q.w * kv.w;
        p += __shfl_xor_sync(0xffffffffu, p, 1);
        p += __shfl_xor_sync(0xffffffffu, p, 2);
        float raw = p * scale;
        if ((lane & 3) == 0) rawb[(size_t)e * NHEAD + h] = raw;
        m_lf = fmaxf(m_lf, raw);
        m_hf = fmaxf(m_hf, 1.0f / (raw + 1e-6f));
    }
    float z_lf = 0.f, z_hf = 0.f;
    float4 alt = make_float4(0.f, 0.f, 0.f, 0.f);
    float4 aht = make_float4(0.f, 0.f, 0.f, 0.f);
    for (int e = beg; e < end; e++) {
        int s = elist[e];
        float rl = 0.f;
        if ((lane & 3) == 0) rl = rawb[(size_t)e * NHEAD + h];
        float raw = __shfl_sync(0xffffffffu, rl, lane & ~3);
        float elf = __expf(raw - m_lf);
        float ehf = __expf(1.0f / (raw + 1e-6f) - m_hf);
        z_lf += elf; z_hf += ehf;
        float4 v = *(const float4*)(V + (size_t)s * DIM + lane * 4);
        alt.x += v.x * elf; alt.y += v.y * elf; alt.z += v.z * elf; alt.w += v.w * elf;
        aht.x += v.x * ehf; aht.y += v.y * ehf; aht.z += v.z * ehf; aht.w += v.w * ehf;
    }
    float izl = (end > beg) ? 1.0f / z_lf : 0.f;
    float izh = (end > beg) ? 1.0f / z_hf : 0.f;
    *(float4*)(lt_out + (size_t)warp * DIM + lane * 4) =
        make_float4(alt.x * izl, alt.y * izl, alt.z * izl, alt.w * izl);
    *(float4*)(ht_out + (size_t)warp * DIM + lane * 4) =
        make_float4(aht.x * izh, aht.y * izh, aht.z * izh, aht.w * izh);
}

// ------------------------- gate scores + blended T -------------------------
__global__ void compute_T(const float* __restrict__ Vr, const float* __restrict__ lta,
                          const float* __restrict__ hta, const float* __restrict__ HZ0,
                          const float* __restrict__ HZ1, const float* __restrict__ XP,
                          float* __restrict__ T, int N)
{
    int warp = (blockIdx.x * blockDim.x + threadIdx.x) >> 5;
    int lane = threadIdx.x & 31;
    if (warp >= N) return;
    size_t base = (size_t)warp * DIM + lane * 4;
    float4 hz0 = *(const float4*)(HZ0 + base);
    float4 hz1 = *(const float4*)(HZ1 + base);
    float4 xp  = *(const float4*)(XP + base);
    float s0 = hz0.x * xp.x + hz0.y * xp.y + hz0.z * xp.z + hz0.w * xp.w;
    float s1 = hz1.x * xp.x + hz1.y * xp.y + hz1.z * xp.z + hz1.w * xp.w;
#pragma unroll
    for (int o = 16; o > 0; o >>= 1) {
        s0 += __shfl_xor_sync(0xffffffffu, s0, o);
        s1 += __shfl_xor_sync(0xffffffffu, s1, o);
    }
    float m = fmaxf(s0, s1);
    float e0 = __expf(s0 - m), e1 = __expf(s1 - m);
    float inv = 1.0f / (e0 + e1);
    float sc0 = e0 * inv, sc1 = e1 * inv;
    float4 ori = *(const float4*)(Vr + base);
    float4 la  = *(const float4*)(lta + base);
    float4 ha  = *(const float4*)(hta + base);
    float4 t;
    t.x = (ori.x + la.x) * sc0 + (ori.x - ha.x) * sc1;
    t.y = (ori.y + la.y) * sc0 + (ori.y - ha.y) * sc1;
    t.z = (ori.z + la.z) * sc0 + (ori.z - ha.z) * sc1;
    t.w = (ori.w + la.w) * sc0 + (ori.w - ha.w) * sc1;
    *(float4*)(T + base) = t;
}

// ------------------------- launch -------------------------
extern "C" void kernel_launch(void* const* d_in, const int* in_sizes, int n_in,
                              void* d_out, int out_size) {
    const float* h_user = (const float*)d_in[0];
    const float* h_item = (const float*)d_in[1];
    const int* buys_src = (const int*)d_in[2];
    const int* buys_dst = (const int*)d_in[3];
    const int* rev_src  = (const int*)d_in[4];
    const int* rev_dst  = (const int*)d_in[5];
    const float* Wk_u = (const float*)d_in[6];  const float* bk_u = (const float*)d_in[7];
    const float* Wk_i = (const float*)d_in[8];  const float* bk_i = (const float*)d_in[9];
    const float* Wq_u = (const float*)d_in[10]; const float* bq_u = (const float*)d_in[11];
    const float* Wq_i = (const float*)d_in[12]; const float* bq_i = (const float*)d_in[13];
    const float* Wv_u = (const float*)d_in[14]; const float* bv_u = (const float*)d_in[15];
    const float* Wv_i = (const float*)d_in[16]; const float* bv_i = (const float*)d_in[17];
    const float* Wa_u = (const float*)d_in[18]; const float* ba_u = (const float*)d_in[19];
    const float* Wa_i = (const float*)d_in[20]; const float* ba_i = (const float*)d_in[21];
    const float* Wf = (const float*)d_in[22];   const float* bf = (const float*)d_in[23];
    const float* Wx = (const float*)d_in[24];   const float* bx = (const float*)d_in[25];
    const float* rel_pri = (const float*)d_in[26];
    const float* rel_att = (const float*)d_in[27];
    const float* rel_msg = (const float*)d_in[28];
    const float* skip = (const float*)d_in[29];
    float* out_u = (float*)d_out;
    float* out_i = (float*)d_out + (size_t)NNODE * DIM;

    float *Ku, *Ki, *Qu, *Qi, *Vru, *Vri, *Vtu, *Vti;
    float *ltu, *htu, *lti, *hti, *HZ0, *HZ1, *XP, *T, *rawb;
    float *fWku, *fbku, *fWki, *fbki, *fWvu, *fbvu, *fWvi, *fbvi;
    int *counts, *cursor, *offsets, *elist, *bsums;
#define SYM(p, s) cudaGetSymbolAddress((void**)&p, s)
    SYM(Ku, g_Ku); SYM(Ki, g_Ki); SYM(Qu, g_Qu); SYM(Qi, g_Qi);
    SYM(Vru, g_Vru); SYM(Vri, g_Vri); SYM(Vtu, g_Vtu); SYM(Vti, g_Vti);
    SYM(ltu, g_ltu); SYM(htu, g_htu); SYM(lti, g_lti); SYM(hti, g_hti);
    SYM(HZ0, g_HZ0); SYM(HZ1, g_HZ1); SYM(XP, g_XP); SYM(T, g_T); SYM(rawb, g_raw);
    SYM(counts, g_counts); SYM(cursor, g_cursor); SYM(offsets, g_offsets); SYM(elist, g_elist);
    SYM(bsums, g_bsums);
    SYM(fWku, g_fWku); SYM(fbku, g_fbku); SYM(fWki, g_fWki); SYM(fbki, g_fbki);
    SYM(fWvu, g_fWvu); SYM(fbvu, g_fbvu); SYM(fWvi, g_fWvi); SYM(fbvi, g_fbvi);
#undef SYM

    const int gemmGridBF = (NNODE + BM - 1) / BM;
    const int gemmGridFP = (NNODE + 63) / 64;
    const int fuseGrid = (DIM * DIM + DIM + 255) / 256;
    const int edgeGrid = (NEDGE + 255) / 256;
    const int warpGrid = (NNODE * 32 + 255) / 256;
    const int zeroGrid = (NNODE + 255) / 256;
    const int scanBlocks = (NNODE + 1023) / 1024;

    // 1) fused weights: K (rel_att folded) and V-msg (rel_msg folded)
    fuse_k<<<fuseGrid, 256>>>(Wk_u, bk_u, rel_att, fWku, fbku);
    fuse_k<<<fuseGrid, 256>>>(Wk_i, bk_i, rel_att + NHEAD * 256, fWki, fbki);
    fuse_k<<<fuseGrid, 256>>>(Wv_u, bv_u, rel_msg, fWvu, fbvu);
    fuse_k<<<fuseGrid, 256>>>(Wv_i, bv_i, rel_msg + NHEAD * 256, fWvi, fbvi);

    // 2) projections: K/Q exact fp32 (pole-sensitive), V + V-msg in bf16x3
    gemm128_fp32<<<gemmGridFP, 256>>>(h_user, fWku, fbku, Ku, NNODE);
    gemm128_fp32<<<gemmGridFP, 256>>>(h_user, Wq_u, bq_u, Qu, NNODE);
    gemm128_fp32<<<gemmGridFP, 256>>>(h_item, fWki, fbki, Ki, NNODE);
    gemm128_fp32<<<gemmGridFP, 256>>>(h_item, Wq_i, bq_i, Qi, NNODE);
    gemm128_bf16<0,0,0><<<gemmGridBF, 256>>>(h_user, nullptr, Wv_u, bv_u, nullptr, nullptr, Vru, NNODE);
    gemm128_bf16<0,0,0><<<gemmGridBF, 256>>>(h_item, nullptr, Wv_i, bv_i, nullptr, nullptr, Vri, NNODE);
    gemm128_bf16<0,0,0><<<gemmGridBF, 256>>>(h_user, nullptr, fWvu, fbvu, nullptr, nullptr, Vtu, NNODE);
    gemm128_bf16<0,0,0><<<gemmGridBF, 256>>>(h_item, nullptr, fWvi, fbvi, nullptr, nullptr, Vti, NNODE);

    // 3) relation 0: user -buys-> item  (dst = items)
    zero_ints<<<zeroGrid, 256>>>(counts, NNODE);
    count_edges<<<edgeGrid, 256>>>(buys_dst, counts);
    scan_blocks<<<scanBlocks, 1024>>>(counts, offsets, bsums, NNODE);
    scan_sums<<<1, 64>>>(bsums, scanBlocks);
    add_carry<<<scanBlocks, 1024>>>(offsets, bsums, cursor, NNODE);
    scatter_edges<<<edgeGrid, 256>>>(buys_src, buys_dst, offsets, cursor, elist);
    attn_agg<<<warpGrid, 256>>>(Qi, Ku, Vtu, offsets, elist, rel_pri, rawb, lti, hti, NNODE);

    // 4) relation 1: item -rev-> user  (dst = users)
    zero_ints<<<zeroGrid, 256>>>(counts, NNODE);
    count_edges<<<edgeGrid, 256>>>(rev_dst, counts);
    scan_blocks<<<scanBlocks, 1024>>>(counts, offsets, bsums, NNODE);
    scan_sums<<<1, 64>>>(bsums, scanBlocks);
    add_carry<<<scanBlocks, 1024>>>(offsets, bsums, cursor, NNODE);
    scatter_edges<<<edgeGrid, 256>>>(rev_src, rev_dst, offsets, cursor, elist);
    attn_agg<<<warpGrid, 256>>>(Qu, Ki, Vti, offsets, elist, rel_pri + NHEAD, rawb, ltu, htu, NNODE);

    // 5) user update
    gemm128_bf16<1,1,0><<<gemmGridBF, 256>>>(Vru, ltu, Wf, bf, nullptr, nullptr, HZ0, NNODE);
    gemm128_bf16<2,1,0><<<gemmGridBF, 256>>>(Vru, htu, Wf, bf, nullptr, nullptr, HZ1, NNODE);
    gemm128_bf16<0,1,0><<<gemmGridBF, 256>>>(Vru, nullptr, Wx, bx, nullptr, nullptr, XP, NNODE);
    compute_T<<<warpGrid, 256>>>(Vru, ltu, htu, HZ0, HZ1, XP, T, NNODE);
    gemm128_bf16<0,0,1><<<gemmGridBF, 256>>>(T, nullptr, Wa_u, ba_u, h_user, skip + 0, out_u, NNODE);

    // 6) item update
    gemm128_bf16<1,1,0><<<gemmGridBF, 256>>>(Vri, lti, Wf, bf, nullptr, nullptr, HZ0, NNODE);
    gemm128_bf16<2,1,0><<<gemmGridBF, 256>>>(Vri, hti, Wf, bf, nullptr, nullptr, HZ1, NNODE);
    gemm128_bf16<0,1,0><<<gemmGridBF, 256>>>(Vri, nullptr, Wx, bx, nullptr, nullptr, XP, NNODE);
    compute_T<<<warpGrid, 256>>>(Vri, lti, hti, HZ0, HZ1, XP, T, NNODE);
    gemm128_bf16<0,0,1><<<gemmGridBF, 256>>>(T, nullptr, Wa_i, ba_i, h_item, skip + 1, out_i, NNODE);
}

// round 9
// speedup vs baseline: 1.4268x; 1.0273x over previous
#include <cuda_runtime.h>
#include <cuda_bf16.h>
#include <math.h>

#define NNODE 50000
#define DIM   128
#define NEDGE 400000
#define NHEAD 8

// ------------------------- device scratch (no allocs allowed) -------------------------
__device__ float g_Ku[NNODE*DIM];
__device__ float g_Ki[NNODE*DIM];
__device__ float g_Qu[NNODE*DIM];
__device__ float g_Qi[NNODE*DIM];
__device__ float g_Vru[NNODE*DIM];
__device__ float g_Vri[NNODE*DIM];
__device__ float g_Vtu[NNODE*DIM];
__device__ float g_Vti[NNODE*DIM];
__device__ float g_ltu[NNODE*DIM];
__device__ float g_htu[NNODE*DIM];
__device__ float g_lti[NNODE*DIM];
__device__ float g_hti[NNODE*DIM];
__device__ float g_HZ0[NNODE*DIM];
__device__ float g_HZ1[NNODE*DIM];
__device__ float g_XP[NNODE*DIM];
__device__ float g_T[NNODE*DIM];
__device__ float g_raw[(size_t)2*NEDGE*NHEAD];
__device__ int   g_counts[2*NNODE];
__device__ int   g_cursor[2*NNODE];
__device__ int   g_offsets[2*NNODE+1];
__device__ int   g_bsums[128];
__device__ int   g_elist[2*NEDGE];
__device__ float g_fWku[DIM*DIM];
__device__ float g_fbku[DIM];
__device__ float g_fWki[DIM*DIM];
__device__ float g_fbki[DIM];
__device__ float g_fWvu[DIM*DIM];
__device__ float g_fbvu[DIM];
__device__ float g_fWvi[DIM*DIM];
__device__ float g_fbvi[DIM];

// ------------------------- zero an int buffer -------------------------
__global__ void zero_ints(int* __restrict__ p, int n) {
    int i = blockIdx.x * blockDim.x + threadIdx.x;
    if (i < n) p[i] = 0;
}

// --------------- fused weight build x4: W' = W @ blockdiag(R) (one launch) ---------------
__global__ void fuse_k4(const float* W0, const float* b0, const float* R0, float* fW0, float* fb0,
                        const float* W1, const float* b1, const float* R1, float* fW1, float* fb1,
                        const float* W2, const float* b2, const float* R2, float* fW2, float* fb2,
                        const float* W3, const float* b3, const float* R3, float* fW3, float* fb3) {
    int s = blockIdx.y;
    const float* Wk = s == 0 ? W0 : s == 1 ? W1 : s == 2 ? W2 : W3;
    const float* bk = s == 0 ? b0 : s == 1 ? b1 : s == 2 ? b2 : b3;
    const float* ra = s == 0 ? R0 : s == 1 ? R1 : s == 2 ? R2 : R3;
    float* fW = s == 0 ? fW0 : s == 1 ? fW1 : s == 2 ? fW2 : fW3;
    float* fb = s == 0 ? fb0 : s == 1 ? fb1 : s == 2 ? fb2 : fb3;
    int idx = blockIdx.x * blockDim.x + threadIdx.x;
    if (idx < DIM * DIM) {
        int j = idx >> 7, c = idx & 127;
        int h = c >> 4, k = c & 15;
        float sm = 0.f;
#pragma unroll
        for (int d = 0; d < 16; d++)
            sm += Wk[(j << 7) + (h << 4) + d] * ra[(h * 16 + d) * 16 + k];
        fW[idx] = sm;
    } else if (idx < DIM * DIM + DIM) {
        int c = idx - DIM * DIM;
        int h = c >> 4, k = c & 15;
        float sm = 0.f;
#pragma unroll
        for (int d = 0; d < 16; d++)
            sm += bk[(h << 4) + d] * ra[(h * 16 + d) * 16 + k];
        fb[c] = sm;
    }
}

// ===================== fp32 f32x2-FFMA GEMM with cp.async double buffering =====================
__device__ __forceinline__ unsigned long long pk2(float lo, float hi) {
    unsigned long long r;
    asm("mov.b64 %0, {%1, %2};" : "=l"(r) : "f"(lo), "f"(hi));
    return r;
}
__device__ __forceinline__ void upk2(unsigned long long v, float &lo, float &hi) {
    asm("mov.b64 {%0, %1}, %2;" : "=f"(lo), "=f"(hi) : "l"(v));
}
__device__ __forceinline__ void ffma2(unsigned long long &d, unsigned long long a, unsigned long long b) {
    asm("fma.rn.f32x2 %0, %1, %2, %0;" : "+l"(d) : "l"(a), "l"(b));
}
__device__ __forceinline__ void cpa16(unsigned dst, const void* src, bool ok) {
    int sz = ok ? 16 : 0;
    asm volatile("cp.async.cg.shared.global [%0], [%1], 16, %2;" :: "r"(dst), "l"(src), "r"(sz));
}

#define FBK 16
#define FASTR 20   // A smem row stride (floats): 80B rows, 16B aligned; banks (20m+k)%32 distinct

__global__ __launch_bounds__(256) void gemm128_fp32(
    const float* __restrict__ A, const float* __restrict__ W, const float* __restrict__ bias,
    float* __restrict__ C, int N)
{
    __shared__ __align__(16) float As[2][64 * FASTR];    // [m][k]
    __shared__ __align__(16) float Ws[2][FBK * 128];     // [k][n]
    const int tid = threadIdx.x;
    const int tx = tid & 31, ty = tid >> 5;
    const int rowBase = blockIdx.x * 64;

    unsigned long long acc[8][2];
#pragma unroll
    for (int r = 0; r < 8; r++) { acc[r][0] = 0ull; acc[r][1] = 0ull; }

    // prefetch lambda: load k-chunk k0 into buffer b
    const int arow = tid >> 2, ach = (tid & 3) * 4;          // A: 1 chunk/thread (64 rows x 4 chunks)
    const bool aok = (rowBase + arow) < N;
    const int wkr0 = tid >> 5, wch = (tid & 31) * 4;         // W: 2 chunks/thread (16 rows x 32 chunks)

#define PREFETCH(b, k0)  do {                                                        \
        cpa16((unsigned)__cvta_generic_to_shared(&As[b][arow * FASTR + ach]),        \
              A + (size_t)(rowBase + arow) * DIM + (k0) + ach, aok);                 \
        cpa16((unsigned)__cvta_generic_to_shared(&Ws[b][(wkr0) * 128 + wch]),        \
              W + (size_t)((k0) + wkr0) * DIM + wch, true);                          \
        cpa16((unsigned)__cvta_generic_to_shared(&Ws[b][(wkr0 + 8) * 128 + wch]),    \
              W + (size_t)((k0) + wkr0 + 8) * DIM + wch, true);                      \
        asm volatile("cp.async.commit_group;");                                      \
    } while (0)

    int buf = 0;
    PREFETCH(0, 0);
    for (int k0i = 0; k0i < 8; k0i++) {
        if (k0i < 7) {
            PREFETCH(buf ^ 1, (k0i + 1) * FBK);
            asm volatile("cp.async.wait_group 1;");
        } else {
            asm volatile("cp.async.wait_group 0;");
        }
        __syncthreads();
        const float* Ab = &As[buf][ty * 8 * FASTR];
        const float* Wb = &Ws[buf][0];
#pragma unroll
        for (int k = 0; k < FBK; k++) {
            float4 w = *(const float4*)&Wb[k * 128 + tx * 4];
            unsigned long long wp0 = pk2(w.x, w.y);
            unsigned long long wp1 = pk2(w.z, w.w);
#pragma unroll
            for (int r = 0; r < 8; r++) {
                float av = Ab[r * FASTR + k];
                unsigned long long ap = pk2(av, av);
                ffma2(acc[r][0], ap, wp0);
                ffma2(acc[r][1], ap, wp1);
            }
        }
        __syncthreads();
        buf ^= 1;
    }
#undef PREFETCH

    const int col = tx * 4;
    float b0 = bias[col], b1 = bias[col + 1], b2 = bias[col + 2], b3 = bias[col + 3];
#pragma unroll
    for (int r = 0; r < 8; r++) {
        int grow = rowBase + ty * 8 + r;
        if (grow < N) {
            float o0, o1, o2, o3;
            upk2(acc[r][0], o0, o1); upk2(acc[r][1], o2, o3);
            *(float4*)(C + (size_t)grow * DIM + col) =
                make_float4(o0 + b0, o1 + b1, o2 + b2, o3 + b3);
        }
    }
}

// ===================== bf16x3 tensor-core GEMM (V + update path) =====================
#define BM 128
#define BK 32
#define APAD 40
#define BPAD 136

__device__ __forceinline__ void mma_bf16(float* c, const unsigned* a, const unsigned* b) {
    asm volatile(
        "mma.sync.aligned.m16n8k16.row.col.f32.bf16.bf16.f32 "
        "{%0,%1,%2,%3}, {%4,%5,%6,%7}, {%8,%9}, {%0,%1,%2,%3};"
        : "+f"(c[0]), "+f"(c[1]), "+f"(c[2]), "+f"(c[3])
        : "r"(a[0]), "r"(a[1]), "r"(a[2]), "r"(a[3]), "r"(b[0]), "r"(b[1]));
}

template<int MIN_, int ACT_, int MOUT_>
__global__ __launch_bounds__(256) void gemm128_bf16(
    const float* __restrict__ A, const float* __restrict__ A2,
    const float* __restrict__ W, const float* __restrict__ bias,
    const float* __restrict__ Dres, const float* __restrict__ skipp,
    float* __restrict__ C, int N)
{
    __shared__ __align__(16) __nv_bfloat16 Ah[BM * APAD];
    __shared__ __align__(16) __nv_bfloat16 Al[BM * APAD];
    __shared__ __align__(16) __nv_bfloat16 Bh[BK * BPAD];
    __shared__ __align__(16) __nv_bfloat16 Bl[BK * BPAD];

    const int tid = threadIdx.x;
    const int lane = tid & 31;
    const int wid = tid >> 5;
    const int warp_m = (wid >> 2) * 64;
    const int warp_n = (wid & 3) * 32;
    const int rowBase = blockIdx.x * BM;

    float acc[4][4][4];
#pragma unroll
    for (int i = 0; i < 4; i++)
#pragma unroll
        for (int j = 0; j < 4; j++)
#pragma unroll
            for (int r = 0; r < 4; r++) acc[i][j][r] = 0.f;

    for (int k0 = 0; k0 < DIM; k0 += BK) {
#pragma unroll
        for (int it = 0; it < 4; it++) {
            int idx = tid + it * 256;
            int row = idx >> 3;
            int c4 = (idx & 7) * 4;
            int grow = rowBase + row;
            float4 v = make_float4(0.f, 0.f, 0.f, 0.f);
            if (grow < N) {
                v = *(const float4*)(A + (size_t)grow * DIM + k0 + c4);
                if (MIN_ == 1) {
                    float4 b = *(const float4*)(A2 + (size_t)grow * DIM + k0 + c4);
                    v.x += b.x; v.y += b.y; v.z += b.z; v.w += b.w;
                } else if (MIN_ == 2) {
                    float4 b = *(const float4*)(A2 + (size_t)grow * DIM + k0 + c4);
                    v.x -= b.x; v.y -= b.y; v.z -= b.z; v.w -= b.w;
                }
            }
            float f[4] = {v.x, v.y, v.z, v.w};
            __nv_bfloat16 h[4], l[4];
#pragma unroll
            for (int q = 0; q < 4; q++) {
                h[q] = __float2bfloat16(f[q]);
                l[q] = __float2bfloat16(f[q] - __bfloat162float(h[q]));
            }
            __nv_bfloat162 p;
            p.x = h[0]; p.y = h[1]; *(__nv_bfloat162*)&Ah[row * APAD + c4] = p;
            p.x = h[2]; p.y = h[3]; *(__nv_bfloat162*)&Ah[row * APAD + c4 + 2] = p;
            p.x = l[0]; p.y = l[1]; *(__nv_bfloat162*)&Al[row * APAD + c4] = p;
            p.x = l[2]; p.y = l[3]; *(__nv_bfloat162*)&Al[row * APAD + c4 + 2] = p;
        }
#pragma unroll
        for (int it = 0; it < 4; it++) {
            int idx = tid + it * 256;
            int kr = idx >> 5;
            int c4 = (idx & 31) * 4;
            float4 v = *(const float4*)(W + (size_t)(k0 + kr) * DIM + c4);
            float f[4] = {v.x, v.y, v.z, v.w};
            __nv_bfloat16 h[4], l[4];
#pragma unroll
            for (int q = 0; q < 4; q++) {
                h[q] = __float2bfloat16(f[q]);
                l[q] = __float2bfloat16(f[q] - __bfloat162float(h[q]));
            }
            __nv_bfloat162 p;
            p.x = h[0]; p.y = h[1]; *(__nv_bfloat162*)&Bh[kr * BPAD + c4] = p;
            p.x = h[2]; p.y = h[3]; *(__nv_bfloat162*)&Bh[kr * BPAD + c4 + 2] = p;
            p.x = l[0]; p.y = l[1]; *(__nv_bfloat162*)&Bl[kr * BPAD + c4] = p;
            p.x = l[2]; p.y = l[3]; *(__nv_bfloat162*)&Bl[kr * BPAD + c4 + 2] = p;
        }
        __syncthreads();

#pragma unroll
        for (int ks = 0; ks < BK; ks += 16) {
            unsigned bh[4][2], bl[4][2];
#pragma unroll
            for (int j = 0; j < 4; j++) {
                int r = ks + (lane & 15);
                int cc = warp_n + j * 8;
                unsigned ab = (unsigned)__cvta_generic_to_shared(&Bh[r * BPAD + cc]);
                asm volatile("ldmatrix.sync.aligned.m8n8.x2.trans.shared.b16 {%0,%1}, [%2];"
                             : "=r"(bh[j][0]), "=r"(bh[j][1]) : "r"(ab));
                unsigned abl = (unsigned)__cvta_generic_to_shared(&Bl[r * BPAD + cc]);
                asm volatile("ldmatrix.sync.aligned.m8n8.x2.trans.shared.b16 {%0,%1}, [%2];"
                             : "=r"(bl[j][0]), "=r"(bl[j][1]) : "r"(abl));
            }
#pragma unroll
            for (int i = 0; i < 4; i++) {
                int r = warp_m + i * 16 + (lane & 15);
                int cc = ks + (lane >> 4) * 8;
                unsigned ah[4], al[4];
                unsigned aa = (unsigned)__cvta_generic_to_shared(&Ah[r * APAD + cc]);
                asm volatile("ldmatrix.sync.aligned.m8n8.x4.shared.b16 {%0,%1,%2,%3}, [%4];"
                             : "=r"(ah[0]), "=r"(ah[1]), "=r"(ah[2]), "=r"(ah[3]) : "r"(aa));
                unsigned aal = (unsigned)__cvta_generic_to_shared(&Al[r * APAD + cc]);
                asm volatile("ldmatrix.sync.aligned.m8n8.x4.shared.b16 {%0,%1,%2,%3}, [%4];"
                             : "=r"(al[0]), "=r"(al[1]), "=r"(al[2]), "=r"(al[3]) : "r"(aal));
#pragma unroll
                for (int j = 0; j < 4; j++) {
                    mma_bf16(acc[i][j], ah, bh[j]);
                    mma_bf16(acc[i][j], ah, bl[j]);
                    mma_bf16(acc[i][j], al, bh[j]);
                }
            }
        }
        __syncthreads();
    }

    float alpha = 1.f, onem = 0.f;
    if (MOUT_ == 1) {
        float s = *skipp;
        alpha = 1.f / (1.f + __expf(-s));
        onem = 1.f - alpha;
    }
    const int g = lane >> 2, t = lane & 3;
#pragma unroll
    for (int i = 0; i < 4; i++) {
        int r0 = rowBase + warp_m + i * 16 + g;
        int r1 = r0 + 8;
#pragma unroll
        for (int j = 0; j < 4; j++) {
            int col = warp_n + j * 8 + t * 2;
            float b0 = bias[col], b1 = bias[col + 1];
            float o0 = acc[i][j][0] + b0, o1 = acc[i][j][1] + b1;
            float o2 = acc[i][j][2] + b0, o3 = acc[i][j][3] + b1;
            if (ACT_ == 1) { o0 = tanhf(o0); o1 = tanhf(o1); o2 = tanhf(o2); o3 = tanhf(o3); }
            if (r0 < N) {
                if (MOUT_ == 1) {
                    float2 dr = *(const float2*)(Dres + (size_t)r0 * DIM + col);
                    o0 = o0 * alpha + dr.x * onem;
                    o1 = o1 * alpha + dr.y * onem;
                }
                float2 ov; ov.x = o0; ov.y = o1;
                *(float2*)(C + (size_t)r0 * DIM + col) = ov;
            }
            if (r1 < N) {
                if (MOUT_ == 1) {
                    float2 dr = *(const float2*)(Dres + (size_t)r1 * DIM + col);
                    o2 = o2 * alpha + dr.x * onem;
                    o3 = o3 * alpha + dr.y * onem;
                }
                float2 ov; ov.x = o2; ov.y = o3;
                *(float2*)(C + (size_t)r1 * DIM + col) = ov;
            }
        }
    }
}

// ------------------------- CSR build: BOTH relations in one pass -------------------------
__global__ void count_edges2(const int* __restrict__ bd, const int* __restrict__ rd,
                             int* __restrict__ counts) {
    int e = blockIdx.x * blockDim.x + threadIdx.x;
    if (e < NEDGE) atomicAdd(&counts[bd[e]], 1);
    else if (e < 2 * NEDGE) atomicAdd(&counts[NNODE + rd[e - NEDGE]], 1);
}

__global__ void scan_blocks(const int* __restrict__ counts, int* __restrict__ offsets,
                            int* __restrict__ bsums, int n) {
    __shared__ int sh[1024];
    int tid = threadIdx.x;
    int i = blockIdx.x * 1024 + tid;
    int v = (i < n) ? counts[i] : 0;
    sh[tid] = v;
    __syncthreads();
    for (int off = 1; off < 1024; off <<= 1) {
        int t = (tid >= off) ? sh[tid - off] : 0;
        __syncthreads();
        sh[tid] += t;
        __syncthreads();
    }
    if (i < n) offsets[i + 1] = sh[tid];
    if (tid == 1023) bsums[blockIdx.x] = sh[1023];
}

// parallel exclusive scan of <=128 block sums
__global__ void scan_sums(int* __restrict__ bsums, int nb) {
    __shared__ int sh[128];
    int tid = threadIdx.x;
    int v = (tid < nb) ? bsums[tid] : 0;
    sh[tid] = v;
    __syncthreads();
    for (int off = 1; off < 128; off <<= 1) {
        int t = (tid >= off) ? sh[tid - off] : 0;
        __syncthreads();
        sh[tid] += t;
        __syncthreads();
    }
    if (tid < nb) bsums[tid] = sh[tid] - v;   // exclusive
}

// add carries + zero cursor (fused)
__global__ void add_carry(int* __restrict__ offsets, const int* __restrict__ bsums,
                          int* __restrict__ cursor, int n) {
    int i = blockIdx.x * 1024 + threadIdx.x;
    if (i < n) {
        offsets[i + 1] += bsums[blockIdx.x];
        cursor[i] = 0;
    }
    if (i == 0) offsets[0] = 0;
}

__global__ void scatter_edges2(const int* __restrict__ bs, const int* __restrict__ bd,
                               const int* __restrict__ rs, const int* __restrict__ rd,
                               const int* __restrict__ offsets, int* __restrict__ cursor,
                               int* __restrict__ elist) {
    int e = blockIdx.x * blockDim.x + threadIdx.x;
    if (e < NEDGE) {
        int d = bd[e];
        int p = atomicAdd(&cursor[d], 1);
        elist[offsets[d] + p] = bs[e];
    } else if (e < 2 * NEDGE) {
        int d = NNODE + rd[e - NEDGE];
        int p = atomicAdd(&cursor[d], 1);
        elist[offsets[d] + p] = rs[e - NEDGE];
    }
}

// ------------------------- per-dst edge softmax (both branches) + aggregation -------------------------
__global__ void attn_agg(const float* __restrict__ Q, const float* __restrict__ K,
                         const float* __restrict__ V,
                         const int* __restrict__ offsets, const int* __restrict__ elist,
                         const float* __restrict__ pri,
                         float* __restrict__ rawb,
                         float* __restrict__ lt_out, float* __restrict__ ht_out, int Ndst)
{
    int warp = (blockIdx.x * blockDim.x + threadIdx.x) >> 5;
    int lane = threadIdx.x & 31;
    if (warp >= Ndst) return;
    const int beg = offsets[warp], end = offsets[warp + 1];
    const int h = lane >> 2;
    const float scale = pri[h] * 0.25f;
    float4 q = *(const float4*)(Q + (size_t)warp * DIM + lane * 4);

    float m_lf = __int_as_float(0xff800000);
    float m_hf = m_lf;
    for (int e = beg; e < end; e++) {
        int s = elist[e];
        float4 kv = *(const float4*)(K + (size_t)s * DIM + lane * 4);
        float p = q.x * kv.x + q.y * kv.y + q.z * kv.z + q.w * kv.w;
        p += __shfl_xor_sync(0xffffffffu, p, 1);
        p += __shfl_xor_sync(0xffffffffu, p, 2);
        float raw = p * scale;
        if ((lane & 3) == 0) rawb[(size_t)e * NHEAD + h] = raw;
        m_lf = fmaxf(m_lf, raw);
        m_hf = fmaxf(m_hf, 1.0f / (raw + 1e-6f));
    }
    float z_lf = 0.f, z_hf = 0.f;
    float4 alt = make_float4(0.f, 0.f, 0.f, 0.f);
    float4 aht = make_float4(0.f, 0.f, 0.f, 0.f);
    for (int e = beg; e < end; e++) {
        int s = elist[e];
        float rl = 0.f;
        if ((lane & 3) == 0) rl = rawb[(size_t)e * NHEAD + h];
        float raw = __shfl_sync(0xffffffffu, rl, lane & ~3);
        float elf = __expf(raw - m_lf);
        float ehf = __expf(1.0f / (raw + 1e-6f) - m_hf);
        z_lf += elf; z_hf += ehf;
        float4 v = *(const float4*)(V + (size_t)s * DIM + lane * 4);
        alt.x += v.x * elf; alt.y += v.y * elf; alt.z += v.z * elf; alt.w += v.w * elf;
        aht.x += v.x * ehf; aht.y += v.y * ehf; aht.z += v.z * ehf; aht.w += v.w * ehf;
    }
    float izl = (end > beg) ? 1.0f / z_lf : 0.f;
    float izh = (end > beg) ? 1.0f / z_hf : 0.f;
    *(float4*)(lt_out + (size_t)warp * DIM + lane * 4) =
        make_float4(alt.x * izl, alt.y * izl, alt.z * izl, alt.w * izl);
    *(float4*)(ht_out + (size_t)warp * DIM + lane * 4) =
        make_float4(aht.x * izh, aht.y * izh, aht.z * izh, aht.w * izh);
}

// ------------------------- gate scores + blended T -------------------------
__global__ void compute_T(const float* __restrict__ Vr, const float* __restrict__ lta,
                          const float* __restrict__ hta, const float* __restrict__ HZ0,
                          const float* __restrict__ HZ1, const float* __restrict__ XP,
                          float* __restrict__ T, int N)
{
    int warp = (blockIdx.x * blockDim.x + threadIdx.x) >> 5;
    int lane = threadIdx.x & 31;
    if (warp >= N) return;
    size_t base = (size_t)warp * DIM + lane * 4;
    float4 hz0 = *(const float4*)(HZ0 + base);
    float4 hz1 = *(const float4*)(HZ1 + base);
    float4 xp  = *(const float4*)(XP + base);
    float s0 = hz0.x * xp.x + hz0.y * xp.y + hz0.z * xp.z + hz0.w * xp.w;
    float s1 = hz1.x * xp.x + hz1.y * xp.y + hz1.z * xp.z + hz1.w * xp.w;
#pragma unroll
    for (int o = 16; o > 0; o >>= 1) {
        s0 += __shfl_xor_sync(0xffffffffu, s0, o);
        s1 += __shfl_xor_sync(0xffffffffu, s1, o);
    }
    float m = fmaxf(s0, s1);
    float e0 = __expf(s0 - m), e1 = __expf(s1 - m);
    float inv = 1.0f / (e0 + e1);
    float sc0 = e0 * inv, sc1 = e1 * inv;
    float4 ori = *(const float4*)(Vr + base);
    float4 la  = *(const float4*)(lta + base);
    float4 ha  = *(const float4*)(hta + base);
    float4 t;
    t.x = (ori.x + la.x) * sc0 + (ori.x - ha.x) * sc1;
    t.y = (ori.y + la.y) * sc0 + (ori.y - ha.y) * sc1;
    t.z = (ori.z + la.z) * sc0 + (ori.z - ha.z) * sc1;
    t.w = (ori.w + la.w) * sc0 + (ori.w - ha.w) * sc1;
    *(float4*)(T + base) = t;
}

// ------------------------- launch -------------------------
extern "C" void kernel_launch(void* const* d_in, const int* in_sizes, int n_in,
                              void* d_out, int out_size) {
    const float* h_user = (const float*)d_in[0];
    const float* h_item = (const float*)d_in[1];
    const int* buys_src = (const int*)d_in[2];
    const int* buys_dst = (const int*)d_in[3];
    const int* rev_src  = (const int*)d_in[4];
    const int* rev_dst  = (const int*)d_in[5];
    const float* Wk_u = (const float*)d_in[6];  const float* bk_u = (const float*)d_in[7];
    const float* Wk_i = (const float*)d_in[8];  const float* bk_i = (const float*)d_in[9];
    const float* Wq_u = (const float*)d_in[10]; const float* bq_u = (const float*)d_in[11];
    const float* Wq_i = (const float*)d_in[12]; const float* bq_i = (const float*)d_in[13];
    const float* Wv_u = (const float*)d_in[14]; const float* bv_u = (const float*)d_in[15];
    const float* Wv_i = (const float*)d_in[16]; const float* bv_i = (const float*)d_in[17];
    const float* Wa_u = (const float*)d_in[18]; const float* ba_u = (const float*)d_in[19];
    const float* Wa_i = (const float*)d_in[20]; const float* ba_i = (const float*)d_in[21];
    const float* Wf = (const float*)d_in[22];   const float* bf = (const float*)d_in[23];
    const float* Wx = (const float*)d_in[24];   const float* bx = (const float*)d_in[25];
    const float* rel_pri = (const float*)d_in[26];
    const float* rel_att = (const float*)d_in[27];
    const float* rel_msg = (const float*)d_in[28];
    const float* skip = (const float*)d_in[29];
    float* out_u = (float*)d_out;
    float* out_i = (float*)d_out + (size_t)NNODE * DIM;

    float *Ku, *Ki, *Qu, *Qi, *Vru, *Vri, *Vtu, *Vti;
    float *ltu, *htu, *lti, *hti, *HZ0, *HZ1, *XP, *T, *rawb;
    float *fWku, *fbku, *fWki, *fbki, *fWvu, *fbvu, *fWvi, *fbvi;
    int *counts, *cursor, *offsets, *elist, *bsums;
#define SYM(p, s) cudaGetSymbolAddress((void**)&p, s)
    SYM(Ku, g_Ku); SYM(Ki, g_Ki); SYM(Qu, g_Qu); SYM(Qi, g_Qi);
    SYM(Vru, g_Vru); SYM(Vri, g_Vri); SYM(Vtu, g_Vtu); SYM(Vti, g_Vti);
    SYM(ltu, g_ltu); SYM(htu, g_htu); SYM(lti, g_lti); SYM(hti, g_hti);
    SYM(HZ0, g_HZ0); SYM(HZ1, g_HZ1); SYM(XP, g_XP); SYM(T, g_T); SYM(rawb, g_raw);
    SYM(counts, g_counts); SYM(cursor, g_cursor); SYM(offsets, g_offsets); SYM(elist, g_elist);
    SYM(bsums, g_bsums);
    SYM(fWku, g_fWku); SYM(fbku, g_fbku); SYM(fWki, g_fWki); SYM(fbki, g_fbki);
    SYM(fWvu, g_fWvu); SYM(fbvu, g_fbvu); SYM(fWvi, g_fWvi); SYM(fbvi, g_fbvi);
#undef SYM

    const int gemmGridBF = (NNODE + BM - 1) / BM;
    const int gemmGridFP = (NNODE + 63) / 64;
    const int edgeGrid2 = (2 * NEDGE + 255) / 256;
    const int warpGrid = (NNODE * 32 + 255) / 256;
    const int zeroGrid2 = (2 * NNODE + 255) / 256;
    const int scanBlocks2 = (2 * NNODE + 1023) / 1024;

    // 1) fused weights (one launch): Ku', Ki' (rel_att), Vu-msg', Vi-msg' (rel_msg)
    dim3 fuseGrid((DIM * DIM + DIM + 255) / 256, 4);
    fuse_k4<<<fuseGrid, 256>>>(
        Wk_u, bk_u, rel_att, fWku, fbku,
        Wk_i, bk_i, rel_att + NHEAD * 256, fWki, fbki,
        Wv_u, bv_u, rel_msg, fWvu, fbvu,
        Wv_i, bv_i, rel_msg + NHEAD * 256, fWvi, fbvi);

    // 2) CSR build for BOTH relations (concatenated, dst-major)
    zero_ints<<<zeroGrid2, 256>>>(counts, 2 * NNODE);
    count_edges2<<<edgeGrid2, 256>>>(buys_dst, rev_dst, counts);
    scan_blocks<<<scanBlocks2, 1024>>>(counts, offsets, bsums, 2 * NNODE);
    scan_sums<<<1, 128>>>(bsums, scanBlocks2);
    add_carry<<<scanBlocks2, 1024>>>(offsets, bsums, cursor, 2 * NNODE);
    scatter_edges2<<<edgeGrid2, 256>>>(buys_src, buys_dst, rev_src, rev_dst, offsets, cursor, elist);

    // 3) projections: K/Q exact fp32 (cp.async pipelined), V + V-msg bf16x3
    gemm128_fp32<<<gemmGridFP, 256>>>(h_user, fWku, fbku, Ku, NNODE);
    gemm128_fp32<<<gemmGridFP, 256>>>(h_user, Wq_u, bq_u, Qu, NNODE);
    gemm128_fp32<<<gemmGridFP, 256>>>(h_item, fWki, fbki, Ki, NNODE);
    gemm128_fp32<<<gemmGridFP, 256>>>(h_item, Wq_i, bq_i, Qi, NNODE);
    gemm128_bf16<0,0,0><<<gemmGridBF, 256>>>(h_user, nullptr, Wv_u, bv_u, nullptr, nullptr, Vru, NNODE);
    gemm128_bf16<0,0,0><<<gemmGridBF, 256>>>(h_item, nullptr, Wv_i, bv_i, nullptr, nullptr, Vri, NNODE);
    gemm128_bf16<0,0,0><<<gemmGridBF, 256>>>(h_user, nullptr, fWvu, fbvu, nullptr, nullptr, Vtu, NNODE);
    gemm128_bf16<0,0,0><<<gemmGridBF, 256>>>(h_item, nullptr, fWvi, fbvi, nullptr, nullptr, Vti, NNODE);

    // 4) attention: rel0 (dst=items, offsets[0..N]), rel1 (dst=users, offsets[N..2N])
    attn_agg<<<warpGrid, 256>>>(Qi, Ku, Vtu, offsets, elist, rel_pri, rawb, lti, hti, NNODE);
    attn_agg<<<warpGrid, 256>>>(Qu, Ki, Vti, offsets + NNODE, elist, rel_pri + NHEAD, rawb, ltu, htu, NNODE);

    // 5) user update
    gemm128_bf16<1,1,0><<<gemmGridBF, 256>>>(Vru, ltu, Wf, bf, nullptr, nullptr, HZ0, NNODE);
    gemm128_bf16<2,1,0><<<gemmGridBF, 256>>>(Vru, htu, Wf, bf, nullptr, nullptr, HZ1, NNODE);
    gemm128_bf16<0,1,0><<<gemmGridBF, 256>>>(Vru, nullptr, Wx, bx, nullptr, nullptr, XP, NNODE);
    compute_T<<<warpGrid, 256>>>(Vru, ltu, htu, HZ0, HZ1, XP, T, NNODE);
    gemm128_bf16<0,0,1><<<gemmGridBF, 256>>>(T, nullptr, Wa_u, ba_u, h_user, skip + 0, out_u, NNODE);

    // 6) item update
    gemm128_bf16<1,1,0><<<gemmGridBF, 256>>>(Vri, lti, Wf, bf, nullptr, nullptr, HZ0, NNODE);
    gemm128_bf16<2,1,0><<<gemmGridBF, 256>>>(Vri, hti, Wf, bf, nullptr, nullptr, HZ1, NNODE);
    gemm128_bf16<0,1,0><<<gemmGridBF, 256>>>(Vri, nullptr, Wx, bx, nullptr, nullptr, XP, NNODE);
    compute_T<<<warpGrid, 256>>>(Vri, lti, hti, HZ0, HZ1, XP, T, NNODE);
    gemm128_bf16<0,0,1><<<gemmGridBF, 256>>>(T, nullptr, Wa_i, ba_i, h_item, skip + 1, out_i, NNODE);
}